// round 5
// baseline (speedup 1.0000x reference)
#include <cuda_runtime.h>
#include <math.h>
#include <stdint.h>

// Problem constants
#define TOKENS 8192      // B*N = 8*1024
#define BATCH  8
#define SEQ    1024
#define C_DIM  768
#define KV_DIM 1536
#define HID    3072
#define HEADS  12
#define DH     64

// ---------------------------------------------------------------------------
// Scratch (device globals -> allowed; no runtime allocation)
// ---------------------------------------------------------------------------
__device__ float g_xn [TOKENS * C_DIM];
__device__ float g_kv [TOKENS * KV_DIM];
__device__ float g_att[TOKENS * C_DIM];
__device__ float g_x2 [TOKENS * C_DIM];
__device__ float g_h  [TOKENS * C_DIM];
__device__ float g_hh [TOKENS * HID];

// ---------------------------------------------------------------------------
// f32x2 packed-FMA helpers (Blackwell FFMA2 — 2 fp32 FMAs per instruction)
// ---------------------------------------------------------------------------
using ull = unsigned long long;

__device__ __forceinline__ ull fma2(ull a, ull b, ull c) {
    ull d;
    asm("fma.rn.f32x2 %0, %1, %2, %3;" : "=l"(d) : "l"(a), "l"(b), "l"(c));
    return d;
}
__device__ __forceinline__ ull pack2(float lo, float hi) {
    ull d;
    asm("mov.b64 %0, {%1, %2};" : "=l"(d) : "f"(lo), "f"(hi));
    return d;
}
__device__ __forceinline__ float2 unpack2(ull v) {
    float2 r;
    asm("mov.b64 {%0, %1}, %2;" : "=f"(r.x), "=f"(r.y) : "l"(v));
    return r;
}

// ---------------------------------------------------------------------------
// LayerNorm: one block per token row of 768. 256 threads, 3 elems each.
// ---------------------------------------------------------------------------
__global__ void __launch_bounds__(256) ln_kernel(
    const float* __restrict__ x, const float* __restrict__ g,
    const float* __restrict__ b, float* __restrict__ out)
{
    __shared__ float sh[9];
    const int row = blockIdx.x;
    const int t = threadIdx.x;
    const float* xr = x + (size_t)row * C_DIM;

    float v0 = xr[t], v1 = xr[t + 256], v2 = xr[t + 512];

    float s = v0 + v1 + v2;
    #pragma unroll
    for (int o = 16; o; o >>= 1) s += __shfl_xor_sync(0xffffffffu, s, o);
    if ((t & 31) == 0) sh[t >> 5] = s;
    __syncthreads();
    if (t == 0) {
        float a = 0.f;
        #pragma unroll
        for (int i = 0; i < 8; i++) a += sh[i];
        sh[8] = a * (1.0f / C_DIM);
    }
    __syncthreads();
    const float mu = sh[8];

    float d0 = v0 - mu, d1 = v1 - mu, d2 = v2 - mu;
    float q = d0 * d0 + d1 * d1 + d2 * d2;
    __syncthreads();   // everyone done reading sh[8] before warp leaders rewrite sh[]
    #pragma unroll
    for (int o = 16; o; o >>= 1) q += __shfl_xor_sync(0xffffffffu, q, o);
    if ((t & 31) == 0) sh[t >> 5] = q;
    __syncthreads();
    if (t == 0) {
        float a = 0.f;
        #pragma unroll
        for (int i = 0; i < 8; i++) a += sh[i];
        sh[8] = rsqrtf(a * (1.0f / C_DIM) + 1e-5f);
    }
    __syncthreads();
    const float rs = sh[8];

    float* orow = out + (size_t)row * C_DIM;
    orow[t]       = d0 * rs * g[t]       + b[t];
    orow[t + 256] = d1 * rs * g[t + 256] + b[t + 256];
    orow[t + 512] = d2 * rs * g[t + 512] + b[t + 512];
}

// ---------------------------------------------------------------------------
// SGEMM 128x128x8, 256 threads, 8x8 per thread, packed f32x2 FMA mainloop.
// A: MxK row-major, B: KxN row-major, C: MxN row-major.
// Epilogue fused: none / +bias+residual / +bias+GELU(exact erf).
// M,N multiples of 128; K multiple of 8 (true for all call sites).
// ---------------------------------------------------------------------------
enum { EPI_NONE = 0, EPI_BIAS_RES = 1, EPI_BIAS_GELU = 2 };

template <int EPI>
__global__ void __launch_bounds__(256) sgemm128(
    int M, int N, int K,
    const float* __restrict__ A, const float* __restrict__ B,
    const float* __restrict__ bias, const float* __restrict__ resid,
    float* __restrict__ C)
{
    __shared__ float As[8][128];   // A transposed: As[k][m]
    __shared__ float Bs[8][128];   // Bs[k][n]

    const int t  = threadIdx.x;
    const int tr = (t >> 4) * 8;       // output row base within tile
    const int tc = (t & 15) * 8;       // output col base within tile
    const int aRow = t >> 1;           // 0..127
    const int aCol = (t & 1) * 4;      // 0 or 4
    const int bRow = t >> 5;           // 0..7
    const int bCol = (t & 31) * 4;     // 0..124

    const float* Ab = A + (size_t)blockIdx.y * 128 * K;
    const float* Bb = B + (size_t)blockIdx.x * 128;

    ull acc[8][4];
    #pragma unroll
    for (int i = 0; i < 8; i++)
        #pragma unroll
        for (int j = 0; j < 4; j++) acc[i][j] = 0ull;  // == (0.f, 0.f)

    for (int k0 = 0; k0 < K; k0 += 8) {
        float4 av = *reinterpret_cast<const float4*>(Ab + (size_t)aRow * K + (k0 + aCol));
        float4 bv = *reinterpret_cast<const float4*>(Bb + (size_t)(k0 + bRow) * N + bCol);
        As[aCol + 0][aRow] = av.x;
        As[aCol + 1][aRow] = av.y;
        As[aCol + 2][aRow] = av.z;
        As[aCol + 3][aRow] = av.w;
        *reinterpret_cast<float4*>(&Bs[bRow][bCol]) = bv;
        __syncthreads();

        #pragma unroll
        for (int kk = 0; kk < 8; ++kk) {
            float4 a0 = *reinterpret_cast<const float4*>(&As[kk][tr]);
            float4 a1 = *reinterpret_cast<const float4*>(&As[kk][tr + 4]);
            float4 b0 = *reinterpret_cast<const float4*>(&Bs[kk][tc]);
            float4 b1 = *reinterpret_cast<const float4*>(&Bs[kk][tc + 4]);
            ull bp0 = pack2(b0.x, b0.y);
            ull bp1 = pack2(b0.z, b0.w);
            ull bp2 = pack2(b1.x, b1.y);
            ull bp3 = pack2(b1.z, b1.w);
            float ra[8] = {a0.x, a0.y, a0.z, a0.w, a1.x, a1.y, a1.z, a1.w};
            #pragma unroll
            for (int i = 0; i < 8; i++) {
                ull ap = pack2(ra[i], ra[i]);
                acc[i][0] = fma2(ap, bp0, acc[i][0]);
                acc[i][1] = fma2(ap, bp1, acc[i][1]);
                acc[i][2] = fma2(ap, bp2, acc[i][2]);
                acc[i][3] = fma2(ap, bp3, acc[i][3]);
            }
        }
        __syncthreads();
    }

    const int row0 = blockIdx.y * 128 + tr;
    const int col0 = blockIdx.x * 128 + tc;
    #pragma unroll
    for (int i = 0; i < 8; i++) {
        const size_t off = (size_t)(row0 + i) * N + col0;
        #pragma unroll
        for (int jp = 0; jp < 4; jp++) {
            float2 v = unpack2(acc[i][jp]);
            const int c = jp * 2;
            float e0 = v.x, e1 = v.y;
            if (EPI != EPI_NONE) {
                e0 += bias[col0 + c];
                e1 += bias[col0 + c + 1];
            }
            if (EPI == EPI_BIAS_RES) {
                e0 += resid[off + c];
                e1 += resid[off + c + 1];
            }
            if (EPI == EPI_BIAS_GELU) {
                e0 = 0.5f * e0 * (1.0f + erff(e0 * 0.70710678118654752f));
                e1 = 0.5f * e1 * (1.0f + erff(e1 * 0.70710678118654752f));
            }
            C[off + c]     = e0;
            C[off + c + 1] = e1;
        }
    }
}

// ---------------------------------------------------------------------------
// Flash attention, fp32. Q from q_extra (no LN). K/V packed in g_kv:
//   k[b,n,h,d] = kv[b,n, h*64+d];  v[b,n,h,d] = kv[b,n, 768 + h*64+d]
// Block: 256 threads = 16x16, each owns a 4x4 of the 64x64 S tile and a
// 4x4 of the 64x64 O tile. Online softmax across 16 K-tiles of 64 rows.
// ---------------------------------------------------------------------------
struct AttSmem {
    float Qs [64][65];
    float KVs[64][65];
    float Ps [64][65];
    float red[64][16];
    float m_run[64];
    float l_run[64];
    float alpha[64];
    float m_cur[64];
};

__global__ void __launch_bounds__(256) attn_kernel(
    const float* __restrict__ qx, const float* __restrict__ kv,
    float* __restrict__ out)
{
    extern __shared__ unsigned char smem_raw[];
    AttSmem& sm = *reinterpret_cast<AttSmem*>(smem_raw);

    const int t  = threadIdx.x;
    const int tx = t & 15, ty = t >> 4;
    const int r0 = ty * 4, c0 = tx * 4;
    const int qb = blockIdx.x * 64;   // q tile base (16 tiles)
    const int h  = blockIdx.y;        // head
    const int b  = blockIdx.z;        // batch

    const float* qptr = qx + ((size_t)b * SEQ) * C_DIM  + (size_t)h * DH;
    const float* kptr = kv + ((size_t)b * SEQ) * KV_DIM + (size_t)h * DH;
    const float* vptr = kptr + C_DIM;   // +768

    // Load Q tile (vectorized float4): 64 rows x 64 dims
    #pragma unroll
    for (int i = 0; i < 4; i++) {
        int vi = t + i * 256;            // 0..1023 float4s
        int r  = vi >> 4;
        int d  = (vi & 15) * 4;
        float4 q4 = *reinterpret_cast<const float4*>(qptr + (size_t)(qb + r) * C_DIM + d);
        sm.Qs[r][d + 0] = q4.x; sm.Qs[r][d + 1] = q4.y;
        sm.Qs[r][d + 2] = q4.z; sm.Qs[r][d + 3] = q4.w;
    }
    if (t < 64) { sm.m_run[t] = -INFINITY; sm.l_run[t] = 0.f; }

    float o[4][4] = {};
    __syncthreads();

    for (int kt = 0; kt < 16; ++kt) {
        const int kb = kt * 64;

        // Load K tile
        #pragma unroll
        for (int i = 0; i < 4; i++) {
            int vi = t + i * 256;
            int r  = vi >> 4;
            int d  = (vi & 15) * 4;
            float4 k4 = *reinterpret_cast<const float4*>(kptr + (size_t)(kb + r) * KV_DIM + d);
            sm.KVs[r][d + 0] = k4.x; sm.KVs[r][d + 1] = k4.y;
            sm.KVs[r][d + 2] = k4.z; sm.KVs[r][d + 3] = k4.w;
        }
        __syncthreads();

        // S = Q @ K^T * scale  (4x4 per thread)
        float s[4][4] = {};
        #pragma unroll 4
        for (int d = 0; d < 64; ++d) {
            float qf[4], kf[4];
            #pragma unroll
            for (int i = 0; i < 4; i++) qf[i] = sm.Qs[r0 + i][d];
            #pragma unroll
            for (int j = 0; j < 4; j++) kf[j] = sm.KVs[c0 + j][d];
            #pragma unroll
            for (int i = 0; i < 4; i++)
                #pragma unroll
                for (int j = 0; j < 4; j++) s[i][j] += qf[i] * kf[j];
        }
        #pragma unroll
        for (int i = 0; i < 4; i++)
            #pragma unroll
            for (int j = 0; j < 4; j++) s[i][j] *= 0.125f;   // DH^-0.5

        __syncthreads();   // KVs reads done; red[] free

        // Row max partials
        #pragma unroll
        for (int i = 0; i < 4; i++) {
            float mx = fmaxf(fmaxf(s[i][0], s[i][1]), fmaxf(s[i][2], s[i][3]));
            sm.red[r0 + i][tx] = mx;
        }
        __syncthreads();

        if (t < 64) {
            float mx = sm.red[t][0];
            #pragma unroll
            for (int jj = 1; jj < 16; jj++) mx = fmaxf(mx, sm.red[t][jj]);
            float mo = sm.m_run[t];
            float mn = fmaxf(mo, mx);
            sm.m_cur[t]  = mn;
            sm.alpha[t]  = expf(mo - mn);
            sm.m_run[t]  = mn;
        }
        __syncthreads();

        // P = exp(S - m_new); write to smem; partial row sums. Also load V.
        #pragma unroll
        for (int i = 0; i < 4; i++) {
            float mn = sm.m_cur[r0 + i];
            float ps = 0.f;
            #pragma unroll
            for (int j = 0; j < 4; j++) {
                float p = expf(s[i][j] - mn);
                sm.Ps[r0 + i][c0 + j] = p;
                ps += p;
            }
            sm.red[r0 + i][tx] = ps;
        }
        #pragma unroll
        for (int i = 0; i < 4; i++) {
            int vi = t + i * 256;
            int r  = vi >> 4;
            int d  = (vi & 15) * 4;
            float4 v4 = *reinterpret_cast<const float4*>(vptr + (size_t)(kb + r) * KV_DIM + d);
            sm.KVs[r][d + 0] = v4.x; sm.KVs[r][d + 1] = v4.y;
            sm.KVs[r][d + 2] = v4.z; sm.KVs[r][d + 3] = v4.w;
        }
        __syncthreads();

        if (t < 64) {
            float su = 0.f;
            #pragma unroll
            for (int jj = 0; jj < 16; jj++) su += sm.red[t][jj];
            sm.l_run[t] = sm.alpha[t] * sm.l_run[t] + su;
        }

        // Rescale O by alpha, then O += P @ V
        #pragma unroll
        for (int i = 0; i < 4; i++) {
            float a = sm.alpha[r0 + i];
            #pragma unroll
            for (int j = 0; j < 4; j++) o[i][j] *= a;
        }
        #pragma unroll 4
        for (int kk = 0; kk < 64; ++kk) {
            float pf[4], vf[4];
            #pragma unroll
            for (int i = 0; i < 4; i++) pf[i] = sm.Ps[r0 + i][kk];
            #pragma unroll
            for (int j = 0; j < 4; j++) vf[j] = sm.KVs[kk][c0 + j];
            #pragma unroll
            for (int i = 0; i < 4; i++)
                #pragma unroll
                for (int j = 0; j < 4; j++) o[i][j] += pf[i] * vf[j];
        }
        __syncthreads();
    }

    // O /= l ; write out[b, qb+r, h*64 + c] (float4 per row)
    #pragma unroll
    for (int i = 0; i < 4; i++) {
        float inv = 1.0f / sm.l_run[r0 + i];
        float4 o4 = make_float4(o[i][0] * inv, o[i][1] * inv, o[i][2] * inv, o[i][3] * inv);
        float* dst = out + ((size_t)b * SEQ + qb + r0 + i) * C_DIM + h * DH + c0;
        *reinterpret_cast<float4*>(dst) = o4;
    }
}

// ---------------------------------------------------------------------------
// Launch
// ---------------------------------------------------------------------------
extern "C" void kernel_launch(void* const* d_in, const int* in_sizes, int n_in,
                              void* d_out, int out_size)
{
    const float* x       = (const float*)d_in[0];
    const float* q_extra = (const float*)d_in[1];
    const float* ln1_g   = (const float*)d_in[2];
    const float* ln1_b   = (const float*)d_in[3];
    const float* w_kv    = (const float*)d_in[4];
    const float* w_out   = (const float*)d_in[5];
    const float* b_out   = (const float*)d_in[6];
    const float* ln2_g   = (const float*)d_in[7];
    const float* ln2_b   = (const float*)d_in[8];
    const float* w1      = (const float*)d_in[9];
    const float* b1      = (const float*)d_in[10];
    const float* w2      = (const float*)d_in[11];
    const float* b2      = (const float*)d_in[12];
    float* out = (float*)d_out;

    float *xn, *kvp, *att, *x2, *h, *hh;
    cudaGetSymbolAddress((void**)&xn,  g_xn);
    cudaGetSymbolAddress((void**)&kvp, g_kv);
    cudaGetSymbolAddress((void**)&att, g_att);
    cudaGetSymbolAddress((void**)&x2,  g_x2);
    cudaGetSymbolAddress((void**)&h,   g_h);
    cudaGetSymbolAddress((void**)&hh,  g_hh);

    cudaFuncSetAttribute(attn_kernel, cudaFuncAttributeMaxDynamicSharedMemorySize,
                         (int)sizeof(AttSmem));

    // 1) xn = LN1(x)
    ln_kernel<<<TOKENS, 256>>>(x, ln1_g, ln1_b, xn);

    // 2) kv = xn @ w_kv                     [8192 x 1536, K=768]
    sgemm128<EPI_NONE><<<dim3(KV_DIM / 128, TOKENS / 128), 256>>>(
        TOKENS, KV_DIM, C_DIM, xn, w_kv, nullptr, nullptr, kvp);

    // 3) att = softmax(q k^T / sqrt(dh)) v
    attn_kernel<<<dim3(SEQ / 64, HEADS, BATCH), 256, sizeof(AttSmem)>>>(q_extra, kvp, att);

    // 4) x2 = x + att @ w_out + b_out       [8192 x 768, K=768]
    sgemm128<EPI_BIAS_RES><<<dim3(C_DIM / 128, TOKENS / 128), 256>>>(
        TOKENS, C_DIM, C_DIM, att, w_out, b_out, x, x2);

    // 5) h = LN2(x2)
    ln_kernel<<<TOKENS, 256>>>(x2, ln2_g, ln2_b, h);

    // 6) hh = gelu(h @ w1 + b1)             [8192 x 3072, K=768]
    sgemm128<EPI_BIAS_GELU><<<dim3(HID / 128, TOKENS / 128), 256>>>(
        TOKENS, HID, C_DIM, h, w1, b1, nullptr, hh);

    // 7) out = x2 + hh @ w2 + b2            [8192 x 768, K=3072]
    sgemm128<EPI_BIAS_RES><<<dim3(C_DIM / 128, TOKENS / 128), 256>>>(
        TOKENS, C_DIM, HID, hh, w2, b2, x2, out);
}

// round 6
// speedup vs baseline: 1.2323x; 1.2323x over previous
#include <cuda_runtime.h>
#include <math.h>
#include <stdint.h>

// Problem constants
#define TOKENS 8192      // B*N = 8*1024
#define BATCH  8
#define SEQ    1024
#define C_DIM  768
#define KV_DIM 1536
#define HID    3072
#define HEADS  12
#define DH     64

// ---------------------------------------------------------------------------
// Scratch (device globals; no runtime allocation)
// ---------------------------------------------------------------------------
__device__ float g_xn [TOKENS * C_DIM];
__device__ float g_kv [TOKENS * KV_DIM];
__device__ float g_att[TOKENS * C_DIM];
__device__ float g_x2 [TOKENS * C_DIM];
__device__ float g_h  [TOKENS * C_DIM];
__device__ float g_hh [TOKENS * HID];

// Pre-split (tf32 hi/lo) weights
__device__ float g_wkv_hi [C_DIM * KV_DIM];
__device__ float g_wkv_lo [C_DIM * KV_DIM];
__device__ float g_wout_hi[C_DIM * C_DIM];
__device__ float g_wout_lo[C_DIM * C_DIM];
__device__ float g_w1_hi  [C_DIM * HID];
__device__ float g_w1_lo  [C_DIM * HID];
__device__ float g_w2_hi  [HID * C_DIM];
__device__ float g_w2_lo  [HID * C_DIM];

// ---------------------------------------------------------------------------
// tf32 helpers
// ---------------------------------------------------------------------------
__device__ __forceinline__ float tf32_rna(float x) {
    uint32_t u;
    asm("cvt.rna.tf32.f32 %0, %1;" : "=r"(u) : "f"(x));
    return __uint_as_float(u);
}

__device__ __forceinline__ void mma_tf32(float* c, const uint32_t* a, const uint32_t* b) {
    asm volatile(
        "mma.sync.aligned.m16n8k8.row.col.f32.tf32.tf32.f32 "
        "{%0,%1,%2,%3}, {%4,%5,%6,%7}, {%8,%9}, {%0,%1,%2,%3};"
        : "+f"(c[0]), "+f"(c[1]), "+f"(c[2]), "+f"(c[3])
        : "r"(a[0]), "r"(a[1]), "r"(a[2]), "r"(a[3]), "r"(b[0]), "r"(b[1]));
}

// Split weights into tf32 hi/lo (runs every launch; ~13us total)
__global__ void __launch_bounds__(256) split_tf32_kernel(
    const float* __restrict__ w, float* __restrict__ hi, float* __restrict__ lo, int n)
{
    int i = blockIdx.x * 256 + threadIdx.x;
    if (i < n) {
        float v = w[i];
        float h = tf32_rna(v);
        hi[i] = h;
        lo[i] = tf32_rna(v - h);
    }
}

// ---------------------------------------------------------------------------
// LayerNorm: one block per token row of 768. 256 threads, 3 elems each.
// ---------------------------------------------------------------------------
__global__ void __launch_bounds__(256) ln_kernel(
    const float* __restrict__ x, const float* __restrict__ g,
    const float* __restrict__ b, float* __restrict__ out)
{
    __shared__ float sh[9];
    const int row = blockIdx.x;
    const int t = threadIdx.x;
    const float* xr = x + (size_t)row * C_DIM;

    float v0 = xr[t], v1 = xr[t + 256], v2 = xr[t + 512];

    float s = v0 + v1 + v2;
    #pragma unroll
    for (int o = 16; o; o >>= 1) s += __shfl_xor_sync(0xffffffffu, s, o);
    if ((t & 31) == 0) sh[t >> 5] = s;
    __syncthreads();
    if (t == 0) {
        float a = 0.f;
        #pragma unroll
        for (int i = 0; i < 8; i++) a += sh[i];
        sh[8] = a * (1.0f / C_DIM);
    }
    __syncthreads();
    const float mu = sh[8];

    float d0 = v0 - mu, d1 = v1 - mu, d2 = v2 - mu;
    float q = d0 * d0 + d1 * d1 + d2 * d2;
    __syncthreads();
    #pragma unroll
    for (int o = 16; o; o >>= 1) q += __shfl_xor_sync(0xffffffffu, q, o);
    if ((t & 31) == 0) sh[t >> 5] = q;
    __syncthreads();
    if (t == 0) {
        float a = 0.f;
        #pragma unroll
        for (int i = 0; i < 8; i++) a += sh[i];
        sh[8] = rsqrtf(a * (1.0f / C_DIM) + 1e-5f);
    }
    __syncthreads();
    const float rs = sh[8];

    float* orow = out + (size_t)row * C_DIM;
    orow[t]       = d0 * rs * g[t]       + b[t];
    orow[t + 256] = d1 * rs * g[t + 256] + b[t + 256];
    orow[t + 512] = d2 * rs * g[t + 512] + b[t + 512];
}

// ---------------------------------------------------------------------------
// Tensor-core GEMM (3xTF32): C = A @ B (+bias)(+resid | GELU)
// A: MxK fp32 row-major (split to tf32 hi/lo on the fly)
// B: KxN pre-split hi/lo row-major
// Block tile 128x128, BK=16, 256 threads = 8 warps (2x4), warp tile 64x32.
// ---------------------------------------------------------------------------
enum { EPI_NONE = 0, EPI_BIAS_RES = 1, EPI_BIAS_GELU = 2 };

#define AST 20     // A smem stride (16 + 4 pad): frag bank = (4g + ti) permutation
#define BST 136    // B smem stride (128 + 8 pad): frag bank = (8ti + g) permutation

template <int EPI>
__global__ void __launch_bounds__(256) tgemm(
    int M, int N, int K,
    const float* __restrict__ A,
    const float* __restrict__ Bhi, const float* __restrict__ Blo,
    const float* __restrict__ bias, const float* __restrict__ resid,
    float* __restrict__ C)
{
    __shared__ float As_hi[128 * AST];
    __shared__ float As_lo[128 * AST];
    __shared__ float Bs_hi[16 * BST];
    __shared__ float Bs_lo[16 * BST];

    const int t    = threadIdx.x;
    const int lane = t & 31;
    const int warp = t >> 5;
    const int wm   = (warp >> 2) * 64;   // 0 or 64
    const int wn   = (warp & 3) * 32;    // 0,32,64,96
    const int g    = lane >> 2;          // 0..7
    const int ti   = lane & 3;           // 0..3

    // global->smem loader indices
    const int aM = t >> 2;               // 0..63 (and +64)
    const int aK = (t & 3) * 4;          // 0,4,8,12
    const int bK = t >> 5;               // 0..7 (and +8)
    const int bN = (t & 31) * 4;         // 0..124

    const float* Ab  = A + ((size_t)blockIdx.y * 128) * K;
    const size_t bcol = (size_t)blockIdx.x * 128;

    float acc[4][4][4];
    #pragma unroll
    for (int i = 0; i < 4; i++)
        #pragma unroll
        for (int j = 0; j < 4; j++)
            #pragma unroll
            for (int k = 0; k < 4; k++) acc[i][j][k] = 0.f;

    float4 aR0, aR1, bh0, bh1, bl0, bl1;

    auto loadG = [&](int s) {
        const int k0 = s * 16;
        aR0 = *reinterpret_cast<const float4*>(Ab + (size_t)aM        * K + k0 + aK);
        aR1 = *reinterpret_cast<const float4*>(Ab + (size_t)(aM + 64) * K + k0 + aK);
        const float* bp = Bhi + (size_t)(k0 + bK) * N + bcol + bN;
        bh0 = *reinterpret_cast<const float4*>(bp);
        bh1 = *reinterpret_cast<const float4*>(bp + (size_t)8 * N);
        const float* bq = Blo + (size_t)(k0 + bK) * N + bcol + bN;
        bl0 = *reinterpret_cast<const float4*>(bq);
        bl1 = *reinterpret_cast<const float4*>(bq + (size_t)8 * N);
    };

    auto storeS = [&]() {
        float4 h, l;
        h.x = tf32_rna(aR0.x); l.x = tf32_rna(aR0.x - h.x);
        h.y = tf32_rna(aR0.y); l.y = tf32_rna(aR0.y - h.y);
        h.z = tf32_rna(aR0.z); l.z = tf32_rna(aR0.z - h.z);
        h.w = tf32_rna(aR0.w); l.w = tf32_rna(aR0.w - h.w);
        *reinterpret_cast<float4*>(&As_hi[aM * AST + aK]) = h;
        *reinterpret_cast<float4*>(&As_lo[aM * AST + aK]) = l;
        h.x = tf32_rna(aR1.x); l.x = tf32_rna(aR1.x - h.x);
        h.y = tf32_rna(aR1.y); l.y = tf32_rna(aR1.y - h.y);
        h.z = tf32_rna(aR1.z); l.z = tf32_rna(aR1.z - h.z);
        h.w = tf32_rna(aR1.w); l.w = tf32_rna(aR1.w - h.w);
        *reinterpret_cast<float4*>(&As_hi[(aM + 64) * AST + aK]) = h;
        *reinterpret_cast<float4*>(&As_lo[(aM + 64) * AST + aK]) = l;
        *reinterpret_cast<float4*>(&Bs_hi[bK       * BST + bN]) = bh0;
        *reinterpret_cast<float4*>(&Bs_hi[(bK + 8) * BST + bN]) = bh1;
        *reinterpret_cast<float4*>(&Bs_lo[bK       * BST + bN]) = bl0;
        *reinterpret_cast<float4*>(&Bs_lo[(bK + 8) * BST + bN]) = bl1;
    };

    const int nStages = K / 16;
    loadG(0);
    storeS();
    __syncthreads();

    for (int s = 0; s < nStages; ++s) {
        if (s + 1 < nStages) loadG(s + 1);

        #pragma unroll
        for (int ks = 0; ks < 16; ks += 8) {
            uint32_t ah[4][4], al[4][4], bh[4][2], bl[4][2];
            #pragma unroll
            for (int i = 0; i < 4; i++) {
                const int mr = (wm + i * 16 + g) * AST + ks + ti;
                ah[i][0] = __float_as_uint(As_hi[mr]);
                ah[i][1] = __float_as_uint(As_hi[mr + 8 * AST]);
                ah[i][2] = __float_as_uint(As_hi[mr + 4]);
                ah[i][3] = __float_as_uint(As_hi[mr + 8 * AST + 4]);
                al[i][0] = __float_as_uint(As_lo[mr]);
                al[i][1] = __float_as_uint(As_lo[mr + 8 * AST]);
                al[i][2] = __float_as_uint(As_lo[mr + 4]);
                al[i][3] = __float_as_uint(As_lo[mr + 8 * AST + 4]);
            }
            #pragma unroll
            for (int j = 0; j < 4; j++) {
                const int nc = (ks + ti) * BST + wn + j * 8 + g;
                bh[j][0] = __float_as_uint(Bs_hi[nc]);
                bh[j][1] = __float_as_uint(Bs_hi[nc + 4 * BST]);
                bl[j][0] = __float_as_uint(Bs_lo[nc]);
                bl[j][1] = __float_as_uint(Bs_lo[nc + 4 * BST]);
            }
            #pragma unroll
            for (int i = 0; i < 4; i++)
                #pragma unroll
                for (int j = 0; j < 4; j++) {
                    mma_tf32(acc[i][j], ah[i], bh[j]);   // hi*hi
                    mma_tf32(acc[i][j], ah[i], bl[j]);   // hi*lo
                    mma_tf32(acc[i][j], al[i], bh[j]);   // lo*hi
                }
        }
        __syncthreads();
        if (s + 1 < nStages) {
            storeS();
            __syncthreads();
        }
    }

    // Epilogue: c0,c1 at (g, 2ti),(g, 2ti+1); c2,c3 at (g+8, ...)
    const int row0 = blockIdx.y * 128 + wm;
    const int col0 = blockIdx.x * 128 + wn;
    #pragma unroll
    for (int i = 0; i < 4; i++) {
        #pragma unroll
        for (int j = 0; j < 4; j++) {
            const int c = col0 + j * 8 + 2 * ti;
            #pragma unroll
            for (int half = 0; half < 2; half++) {
                const int r = row0 + i * 16 + g + half * 8;
                float e0 = acc[i][j][half * 2 + 0];
                float e1 = acc[i][j][half * 2 + 1];
                const size_t off = (size_t)r * N + c;
                if (EPI != EPI_NONE) {
                    e0 += bias[c];
                    e1 += bias[c + 1];
                }
                if (EPI == EPI_BIAS_RES) {
                    float2 rr = *reinterpret_cast<const float2*>(resid + off);
                    e0 += rr.x;
                    e1 += rr.y;
                }
                if (EPI == EPI_BIAS_GELU) {
                    e0 = 0.5f * e0 * (1.0f + erff(e0 * 0.70710678118654752f));
                    e1 = 0.5f * e1 * (1.0f + erff(e1 * 0.70710678118654752f));
                }
                float2 vv = make_float2(e0, e1);
                *reinterpret_cast<float2*>(C + off) = vv;
            }
        }
    }
}

// ---------------------------------------------------------------------------
// Flash attention, fp32 (unchanged from passing R5 kernel).
// ---------------------------------------------------------------------------
struct AttSmem {
    float Qs [64][65];
    float KVs[64][65];
    float Ps [64][65];
    float red[64][16];
    float m_run[64];
    float l_run[64];
    float alpha[64];
    float m_cur[64];
};

__global__ void __launch_bounds__(256) attn_kernel(
    const float* __restrict__ qx, const float* __restrict__ kv,
    float* __restrict__ out)
{
    extern __shared__ unsigned char smem_raw[];
    AttSmem& sm = *reinterpret_cast<AttSmem*>(smem_raw);

    const int t  = threadIdx.x;
    const int tx = t & 15, ty = t >> 4;
    const int r0 = ty * 4, c0 = tx * 4;
    const int qb = blockIdx.x * 64;
    const int h  = blockIdx.y;
    const int b  = blockIdx.z;

    const float* qptr = qx + ((size_t)b * SEQ) * C_DIM  + (size_t)h * DH;
    const float* kptr = kv + ((size_t)b * SEQ) * KV_DIM + (size_t)h * DH;
    const float* vptr = kptr + C_DIM;

    #pragma unroll
    for (int i = 0; i < 4; i++) {
        int vi = t + i * 256;
        int r  = vi >> 4;
        int d  = (vi & 15) * 4;
        float4 q4 = *reinterpret_cast<const float4*>(qptr + (size_t)(qb + r) * C_DIM + d);
        sm.Qs[r][d + 0] = q4.x; sm.Qs[r][d + 1] = q4.y;
        sm.Qs[r][d + 2] = q4.z; sm.Qs[r][d + 3] = q4.w;
    }
    if (t < 64) { sm.m_run[t] = -INFINITY; sm.l_run[t] = 0.f; }

    float o[4][4] = {};
    __syncthreads();

    for (int kt = 0; kt < 16; ++kt) {
        const int kb = kt * 64;

        #pragma unroll
        for (int i = 0; i < 4; i++) {
            int vi = t + i * 256;
            int r  = vi >> 4;
            int d  = (vi & 15) * 4;
            float4 k4 = *reinterpret_cast<const float4*>(kptr + (size_t)(kb + r) * KV_DIM + d);
            sm.KVs[r][d + 0] = k4.x; sm.KVs[r][d + 1] = k4.y;
            sm.KVs[r][d + 2] = k4.z; sm.KVs[r][d + 3] = k4.w;
        }
        __syncthreads();

        float s[4][4] = {};
        #pragma unroll 4
        for (int d = 0; d < 64; ++d) {
            float qf[4], kf[4];
            #pragma unroll
            for (int i = 0; i < 4; i++) qf[i] = sm.Qs[r0 + i][d];
            #pragma unroll
            for (int j = 0; j < 4; j++) kf[j] = sm.KVs[c0 + j][d];
            #pragma unroll
            for (int i = 0; i < 4; i++)
                #pragma unroll
                for (int j = 0; j < 4; j++) s[i][j] += qf[i] * kf[j];
        }
        #pragma unroll
        for (int i = 0; i < 4; i++)
            #pragma unroll
            for (int j = 0; j < 4; j++) s[i][j] *= 0.125f;

        __syncthreads();

        #pragma unroll
        for (int i = 0; i < 4; i++) {
            float mx = fmaxf(fmaxf(s[i][0], s[i][1]), fmaxf(s[i][2], s[i][3]));
            sm.red[r0 + i][tx] = mx;
        }
        __syncthreads();

        if (t < 64) {
            float mx = sm.red[t][0];
            #pragma unroll
            for (int jj = 1; jj < 16; jj++) mx = fmaxf(mx, sm.red[t][jj]);
            float mo = sm.m_run[t];
            float mn = fmaxf(mo, mx);
            sm.m_cur[t]  = mn;
            sm.alpha[t]  = expf(mo - mn);
            sm.m_run[t]  = mn;
        }
        __syncthreads();

        #pragma unroll
        for (int i = 0; i < 4; i++) {
            float mn = sm.m_cur[r0 + i];
            float ps = 0.f;
            #pragma unroll
            for (int j = 0; j < 4; j++) {
                float p = expf(s[i][j] - mn);
                sm.Ps[r0 + i][c0 + j] = p;
                ps += p;
            }
            sm.red[r0 + i][tx] = ps;
        }
        #pragma unroll
        for (int i = 0; i < 4; i++) {
            int vi = t + i * 256;
            int r  = vi >> 4;
            int d  = (vi & 15) * 4;
            float4 v4 = *reinterpret_cast<const float4*>(vptr + (size_t)(kb + r) * KV_DIM + d);
            sm.KVs[r][d + 0] = v4.x; sm.KVs[r][d + 1] = v4.y;
            sm.KVs[r][d + 2] = v4.z; sm.KVs[r][d + 3] = v4.w;
        }
        __syncthreads();

        if (t < 64) {
            float su = 0.f;
            #pragma unroll
            for (int jj = 0; jj < 16; jj++) su += sm.red[t][jj];
            sm.l_run[t] = sm.alpha[t] * sm.l_run[t] + su;
        }

        #pragma unroll
        for (int i = 0; i < 4; i++) {
            float a = sm.alpha[r0 + i];
            #pragma unroll
            for (int j = 0; j < 4; j++) o[i][j] *= a;
        }
        #pragma unroll 4
        for (int kk = 0; kk < 64; ++kk) {
            float pf[4], vf[4];
            #pragma unroll
            for (int i = 0; i < 4; i++) pf[i] = sm.Ps[r0 + i][kk];
            #pragma unroll
            for (int j = 0; j < 4; j++) vf[j] = sm.KVs[kk][c0 + j];
            #pragma unroll
            for (int i = 0; i < 4; i++)
                #pragma unroll
                for (int j = 0; j < 4; j++) o[i][j] += pf[i] * vf[j];
        }
        __syncthreads();
    }

    #pragma unroll
    for (int i = 0; i < 4; i++) {
        float inv = 1.0f / sm.l_run[r0 + i];
        float4 o4 = make_float4(o[i][0] * inv, o[i][1] * inv, o[i][2] * inv, o[i][3] * inv);
        float* dst = out + ((size_t)b * SEQ + qb + r0 + i) * C_DIM + h * DH + c0;
        *reinterpret_cast<float4*>(dst) = o4;
    }
}

// ---------------------------------------------------------------------------
// Launch
// ---------------------------------------------------------------------------
extern "C" void kernel_launch(void* const* d_in, const int* in_sizes, int n_in,
                              void* d_out, int out_size)
{
    const float* x       = (const float*)d_in[0];
    const float* q_extra = (const float*)d_in[1];
    const float* ln1_g   = (const float*)d_in[2];
    const float* ln1_b   = (const float*)d_in[3];
    const float* w_kv    = (const float*)d_in[4];
    const float* w_out   = (const float*)d_in[5];
    const float* b_out   = (const float*)d_in[6];
    const float* ln2_g   = (const float*)d_in[7];
    const float* ln2_b   = (const float*)d_in[8];
    const float* w1      = (const float*)d_in[9];
    const float* b1      = (const float*)d_in[10];
    const float* w2      = (const float*)d_in[11];
    const float* b2      = (const float*)d_in[12];
    float* out = (float*)d_out;

    float *xn, *kvp, *att, *x2, *h, *hh;
    cudaGetSymbolAddress((void**)&xn,  g_xn);
    cudaGetSymbolAddress((void**)&kvp, g_kv);
    cudaGetSymbolAddress((void**)&att, g_att);
    cudaGetSymbolAddress((void**)&x2,  g_x2);
    cudaGetSymbolAddress((void**)&h,   g_h);
    cudaGetSymbolAddress((void**)&hh,  g_hh);

    float *wkv_hi, *wkv_lo, *wout_hi, *wout_lo, *w1_hi, *w1_lo, *w2_hi, *w2_lo;
    cudaGetSymbolAddress((void**)&wkv_hi,  g_wkv_hi);
    cudaGetSymbolAddress((void**)&wkv_lo,  g_wkv_lo);
    cudaGetSymbolAddress((void**)&wout_hi, g_wout_hi);
    cudaGetSymbolAddress((void**)&wout_lo, g_wout_lo);
    cudaGetSymbolAddress((void**)&w1_hi,   g_w1_hi);
    cudaGetSymbolAddress((void**)&w1_lo,   g_w1_lo);
    cudaGetSymbolAddress((void**)&w2_hi,   g_w2_hi);
    cudaGetSymbolAddress((void**)&w2_lo,   g_w2_lo);

    cudaFuncSetAttribute(attn_kernel, cudaFuncAttributeMaxDynamicSharedMemorySize,
                         (int)sizeof(AttSmem));

    // 0) Pre-split weights to tf32 hi/lo
    {
        int n;
        n = C_DIM * KV_DIM; split_tf32_kernel<<<(n + 255) / 256, 256>>>(w_kv, wkv_hi, wkv_lo, n);
        n = C_DIM * C_DIM;  split_tf32_kernel<<<(n + 255) / 256, 256>>>(w_out, wout_hi, wout_lo, n);
        n = C_DIM * HID;    split_tf32_kernel<<<(n + 255) / 256, 256>>>(w1, w1_hi, w1_lo, n);
        n = HID * C_DIM;    split_tf32_kernel<<<(n + 255) / 256, 256>>>(w2, w2_hi, w2_lo, n);
    }

    // 1) xn = LN1(x)
    ln_kernel<<<TOKENS, 256>>>(x, ln1_g, ln1_b, xn);

    // 2) kv = xn @ w_kv                     [8192 x 1536, K=768]
    tgemm<EPI_NONE><<<dim3(KV_DIM / 128, TOKENS / 128), 256>>>(
        TOKENS, KV_DIM, C_DIM, xn, wkv_hi, wkv_lo, nullptr, nullptr, kvp);

    // 3) att = softmax(q k^T / sqrt(dh)) v
    attn_kernel<<<dim3(SEQ / 64, HEADS, BATCH), 256, sizeof(AttSmem)>>>(q_extra, kvp, att);

    // 4) x2 = x + att @ w_out + b_out       [8192 x 768, K=768]
    tgemm<EPI_BIAS_RES><<<dim3(C_DIM / 128, TOKENS / 128), 256>>>(
        TOKENS, C_DIM, C_DIM, att, wout_hi, wout_lo, b_out, x, x2);

    // 5) h = LN2(x2)
    ln_kernel<<<TOKENS, 256>>>(x2, ln2_g, ln2_b, h);

    // 6) hh = gelu(h @ w1 + b1)             [8192 x 3072, K=768]
    tgemm<EPI_BIAS_GELU><<<dim3(HID / 128, TOKENS / 128), 256>>>(
        TOKENS, HID, C_DIM, h, w1_hi, w1_lo, b1, nullptr, hh);

    // 7) out = x2 + hh @ w2 + b2            [8192 x 768, K=3072]
    tgemm<EPI_BIAS_RES><<<dim3(C_DIM / 128, TOKENS / 128), 256>>>(
        TOKENS, C_DIM, HID, hh, w2_hi, w2_lo, b2, x2, out);
}

// round 7
// speedup vs baseline: 1.2328x; 1.0004x over previous
#include <cuda_runtime.h>
#include <math.h>
#include <stdint.h>

// Problem constants
#define TOKENS 8192      // B*N = 8*1024
#define BATCH  8
#define SEQ    1024
#define C_DIM  768
#define KV_DIM 1536
#define HID    3072
#define HEADS  12
#define DH     64

// ---------------------------------------------------------------------------
// Scratch (device globals; no runtime allocation)
// ---------------------------------------------------------------------------
__device__ float g_xn [TOKENS * C_DIM];
__device__ float g_kv [TOKENS * KV_DIM];
__device__ float g_att[TOKENS * C_DIM];
__device__ float g_x2 [TOKENS * C_DIM];
__device__ float g_h  [TOKENS * C_DIM];
__device__ float g_hh [TOKENS * HID];

// Pre-split (tf32 hi/lo) weights
__device__ float g_wkv_hi [C_DIM * KV_DIM];
__device__ float g_wkv_lo [C_DIM * KV_DIM];
__device__ float g_wout_hi[C_DIM * C_DIM];
__device__ float g_wout_lo[C_DIM * C_DIM];
__device__ float g_w1_hi  [C_DIM * HID];
__device__ float g_w1_lo  [C_DIM * HID];
__device__ float g_w2_hi  [HID * C_DIM];
__device__ float g_w2_lo  [HID * C_DIM];

// ---------------------------------------------------------------------------
// tf32 helpers
// ---------------------------------------------------------------------------
__device__ __forceinline__ float tf32_rna(float x) {
    uint32_t u;
    asm("cvt.rna.tf32.f32 %0, %1;" : "=r"(u) : "f"(x));
    return __uint_as_float(u);
}

__device__ __forceinline__ void mma_tf32(float* c, const uint32_t* a, const uint32_t* b) {
    asm volatile(
        "mma.sync.aligned.m16n8k8.row.col.f32.tf32.tf32.f32 "
        "{%0,%1,%2,%3}, {%4,%5,%6,%7}, {%8,%9}, {%0,%1,%2,%3};"
        : "+f"(c[0]), "+f"(c[1]), "+f"(c[2]), "+f"(c[3])
        : "r"(a[0]), "r"(a[1]), "r"(a[2]), "r"(a[3]), "r"(b[0]), "r"(b[1]));
}

// Split weights into tf32 hi/lo (runs every launch; ~13us total)
__global__ void __launch_bounds__(256) split_tf32_kernel(
    const float* __restrict__ w, float* __restrict__ hi, float* __restrict__ lo, int n)
{
    int i = blockIdx.x * 256 + threadIdx.x;
    if (i < n) {
        float v = w[i];
        float h = tf32_rna(v);
        hi[i] = h;
        lo[i] = tf32_rna(v - h);
    }
}

// ---------------------------------------------------------------------------
// LayerNorm: one block per token row of 768. 256 threads, 3 elems each.
// ---------------------------------------------------------------------------
__global__ void __launch_bounds__(256) ln_kernel(
    const float* __restrict__ x, const float* __restrict__ g,
    const float* __restrict__ b, float* __restrict__ out)
{
    __shared__ float sh[9];
    const int row = blockIdx.x;
    const int t = threadIdx.x;
    const float* xr = x + (size_t)row * C_DIM;

    float v0 = xr[t], v1 = xr[t + 256], v2 = xr[t + 512];

    float s = v0 + v1 + v2;
    #pragma unroll
    for (int o = 16; o; o >>= 1) s += __shfl_xor_sync(0xffffffffu, s, o);
    if ((t & 31) == 0) sh[t >> 5] = s;
    __syncthreads();
    if (t == 0) {
        float a = 0.f;
        #pragma unroll
        for (int i = 0; i < 8; i++) a += sh[i];
        sh[8] = a * (1.0f / C_DIM);
    }
    __syncthreads();
    const float mu = sh[8];

    float d0 = v0 - mu, d1 = v1 - mu, d2 = v2 - mu;
    float q = d0 * d0 + d1 * d1 + d2 * d2;
    __syncthreads();
    #pragma unroll
    for (int o = 16; o; o >>= 1) q += __shfl_xor_sync(0xffffffffu, q, o);
    if ((t & 31) == 0) sh[t >> 5] = q;
    __syncthreads();
    if (t == 0) {
        float a = 0.f;
        #pragma unroll
        for (int i = 0; i < 8; i++) a += sh[i];
        sh[8] = rsqrtf(a * (1.0f / C_DIM) + 1e-5f);
    }
    __syncthreads();
    const float rs = sh[8];

    float* orow = out + (size_t)row * C_DIM;
    orow[t]       = d0 * rs * g[t]       + b[t];
    orow[t + 256] = d1 * rs * g[t + 256] + b[t + 256];
    orow[t + 512] = d2 * rs * g[t + 512] + b[t + 512];
}

// ---------------------------------------------------------------------------
// Tensor-core GEMM (3xTF32): C = A @ B (+bias)(+resid | GELU)
// A: MxK fp32 row-major (split to tf32 hi/lo on the fly)
// B: KxN pre-split hi/lo row-major
// Block tile 128x128, BK=16, 256 threads = 8 warps (2x4), warp tile 64x32.
// ---------------------------------------------------------------------------
enum { EPI_NONE = 0, EPI_BIAS_RES = 1, EPI_BIAS_GELU = 2 };

#define AST 20     // A smem stride (16 + 4 pad): frag bank = (4g + ti) permutation
#define BST 136    // B smem stride (128 + 8 pad): frag bank = (8ti + g) permutation

template <int EPI>
__global__ void __launch_bounds__(256) tgemm(
    int M, int N, int K,
    const float* __restrict__ A,
    const float* __restrict__ Bhi, const float* __restrict__ Blo,
    const float* __restrict__ bias, const float* __restrict__ resid,
    float* __restrict__ C)
{
    __shared__ float As_hi[128 * AST];
    __shared__ float As_lo[128 * AST];
    __shared__ float Bs_hi[16 * BST];
    __shared__ float Bs_lo[16 * BST];

    const int t    = threadIdx.x;
    const int lane = t & 31;
    const int warp = t >> 5;
    const int wm   = (warp >> 2) * 64;   // 0 or 64
    const int wn   = (warp & 3) * 32;    // 0,32,64,96
    const int g    = lane >> 2;          // 0..7
    const int ti   = lane & 3;           // 0..3

    // global->smem loader indices
    const int aM = t >> 2;               // 0..63 (and +64)
    const int aK = (t & 3) * 4;          // 0,4,8,12
    const int bK = t >> 5;               // 0..7 (and +8)
    const int bN = (t & 31) * 4;         // 0..124

    const float* Ab  = A + ((size_t)blockIdx.y * 128) * K;
    const size_t bcol = (size_t)blockIdx.x * 128;

    float acc[4][4][4];
    #pragma unroll
    for (int i = 0; i < 4; i++)
        #pragma unroll
        for (int j = 0; j < 4; j++)
            #pragma unroll
            for (int k = 0; k < 4; k++) acc[i][j][k] = 0.f;

    float4 aR0, aR1, bh0, bh1, bl0, bl1;

    auto loadG = [&](int s) {
        const int k0 = s * 16;
        aR0 = *reinterpret_cast<const float4*>(Ab + (size_t)aM        * K + k0 + aK);
        aR1 = *reinterpret_cast<const float4*>(Ab + (size_t)(aM + 64) * K + k0 + aK);
        const float* bp = Bhi + (size_t)(k0 + bK) * N + bcol + bN;
        bh0 = *reinterpret_cast<const float4*>(bp);
        bh1 = *reinterpret_cast<const float4*>(bp + (size_t)8 * N);
        const float* bq = Blo + (size_t)(k0 + bK) * N + bcol + bN;
        bl0 = *reinterpret_cast<const float4*>(bq);
        bl1 = *reinterpret_cast<const float4*>(bq + (size_t)8 * N);
    };

    auto storeS = [&]() {
        float4 h, l;
        h.x = tf32_rna(aR0.x); l.x = tf32_rna(aR0.x - h.x);
        h.y = tf32_rna(aR0.y); l.y = tf32_rna(aR0.y - h.y);
        h.z = tf32_rna(aR0.z); l.z = tf32_rna(aR0.z - h.z);
        h.w = tf32_rna(aR0.w); l.w = tf32_rna(aR0.w - h.w);
        *reinterpret_cast<float4*>(&As_hi[aM * AST + aK]) = h;
        *reinterpret_cast<float4*>(&As_lo[aM * AST + aK]) = l;
        h.x = tf32_rna(aR1.x); l.x = tf32_rna(aR1.x - h.x);
        h.y = tf32_rna(aR1.y); l.y = tf32_rna(aR1.y - h.y);
        h.z = tf32_rna(aR1.z); l.z = tf32_rna(aR1.z - h.z);
        h.w = tf32_rna(aR1.w); l.w = tf32_rna(aR1.w - h.w);
        *reinterpret_cast<float4*>(&As_hi[(aM + 64) * AST + aK]) = h;
        *reinterpret_cast<float4*>(&As_lo[(aM + 64) * AST + aK]) = l;
        *reinterpret_cast<float4*>(&Bs_hi[bK       * BST + bN]) = bh0;
        *reinterpret_cast<float4*>(&Bs_hi[(bK + 8) * BST + bN]) = bh1;
        *reinterpret_cast<float4*>(&Bs_lo[bK       * BST + bN]) = bl0;
        *reinterpret_cast<float4*>(&Bs_lo[(bK + 8) * BST + bN]) = bl1;
    };

    const int nStages = K / 16;
    loadG(0);
    storeS();
    __syncthreads();

    for (int s = 0; s < nStages; ++s) {
        if (s + 1 < nStages) loadG(s + 1);

        #pragma unroll
        for (int ks = 0; ks < 16; ks += 8) {
            uint32_t ah[4][4], al[4][4], bh[4][2], bl[4][2];
            #pragma unroll
            for (int i = 0; i < 4; i++) {
                const int mr = (wm + i * 16 + g) * AST + ks + ti;
                ah[i][0] = __float_as_uint(As_hi[mr]);
                ah[i][1] = __float_as_uint(As_hi[mr + 8 * AST]);
                ah[i][2] = __float_as_uint(As_hi[mr + 4]);
                ah[i][3] = __float_as_uint(As_hi[mr + 8 * AST + 4]);
                al[i][0] = __float_as_uint(As_lo[mr]);
                al[i][1] = __float_as_uint(As_lo[mr + 8 * AST]);
                al[i][2] = __float_as_uint(As_lo[mr + 4]);
                al[i][3] = __float_as_uint(As_lo[mr + 8 * AST + 4]);
            }
            #pragma unroll
            for (int j = 0; j < 4; j++) {
                const int nc = (ks + ti) * BST + wn + j * 8 + g;
                bh[j][0] = __float_as_uint(Bs_hi[nc]);
                bh[j][1] = __float_as_uint(Bs_hi[nc + 4 * BST]);
                bl[j][0] = __float_as_uint(Bs_lo[nc]);
                bl[j][1] = __float_as_uint(Bs_lo[nc + 4 * BST]);
            }
            #pragma unroll
            for (int i = 0; i < 4; i++)
                #pragma unroll
                for (int j = 0; j < 4; j++) {
                    mma_tf32(acc[i][j], ah[i], bh[j]);   // hi*hi
                    mma_tf32(acc[i][j], ah[i], bl[j]);   // hi*lo
                    mma_tf32(acc[i][j], al[i], bh[j]);   // lo*hi
                }
        }
        __syncthreads();
        if (s + 1 < nStages) {
            storeS();
            __syncthreads();
        }
    }

    // Epilogue: c0,c1 at (g, 2ti),(g, 2ti+1); c2,c3 at (g+8, ...)
    const int row0 = blockIdx.y * 128 + wm;
    const int col0 = blockIdx.x * 128 + wn;
    #pragma unroll
    for (int i = 0; i < 4; i++) {
        #pragma unroll
        for (int j = 0; j < 4; j++) {
            const int c = col0 + j * 8 + 2 * ti;
            #pragma unroll
            for (int half = 0; half < 2; half++) {
                const int r = row0 + i * 16 + g + half * 8;
                float e0 = acc[i][j][half * 2 + 0];
                float e1 = acc[i][j][half * 2 + 1];
                const size_t off = (size_t)r * N + c;
                if (EPI != EPI_NONE) {
                    e0 += bias[c];
                    e1 += bias[c + 1];
                }
                if (EPI == EPI_BIAS_RES) {
                    float2 rr = *reinterpret_cast<const float2*>(resid + off);
                    e0 += rr.x;
                    e1 += rr.y;
                }
                if (EPI == EPI_BIAS_GELU) {
                    e0 = 0.5f * e0 * (1.0f + erff(e0 * 0.70710678118654752f));
                    e1 = 0.5f * e1 * (1.0f + erff(e1 * 0.70710678118654752f));
                }
                float2 vv = make_float2(e0, e1);
                *reinterpret_cast<float2*>(C + off) = vv;
            }
        }
    }
}

// ---------------------------------------------------------------------------
// Flash attention, fp32 (unchanged from passing R5 kernel).
// ---------------------------------------------------------------------------
struct AttSmem {
    float Qs [64][65];
    float KVs[64][65];
    float Ps [64][65];
    float red[64][16];
    float m_run[64];
    float l_run[64];
    float alpha[64];
    float m_cur[64];
};

__global__ void __launch_bounds__(256) attn_kernel(
    const float* __restrict__ qx, const float* __restrict__ kv,
    float* __restrict__ out)
{
    extern __shared__ unsigned char smem_raw[];
    AttSmem& sm = *reinterpret_cast<AttSmem*>(smem_raw);

    const int t  = threadIdx.x;
    const int tx = t & 15, ty = t >> 4;
    const int r0 = ty * 4, c0 = tx * 4;
    const int qb = blockIdx.x * 64;
    const int h  = blockIdx.y;
    const int b  = blockIdx.z;

    const float* qptr = qx + ((size_t)b * SEQ) * C_DIM  + (size_t)h * DH;
    const float* kptr = kv + ((size_t)b * SEQ) * KV_DIM + (size_t)h * DH;
    const float* vptr = kptr + C_DIM;

    #pragma unroll
    for (int i = 0; i < 4; i++) {
        int vi = t + i * 256;
        int r  = vi >> 4;
        int d  = (vi & 15) * 4;
        float4 q4 = *reinterpret_cast<const float4*>(qptr + (size_t)(qb + r) * C_DIM + d);
        sm.Qs[r][d + 0] = q4.x; sm.Qs[r][d + 1] = q4.y;
        sm.Qs[r][d + 2] = q4.z; sm.Qs[r][d + 3] = q4.w;
    }
    if (t < 64) { sm.m_run[t] = -INFINITY; sm.l_run[t] = 0.f; }

    float o[4][4] = {};
    __syncthreads();

    for (int kt = 0; kt < 16; ++kt) {
        const int kb = kt * 64;

        #pragma unroll
        for (int i = 0; i < 4; i++) {
            int vi = t + i * 256;
            int r  = vi >> 4;
            int d  = (vi & 15) * 4;
            float4 k4 = *reinterpret_cast<const float4*>(kptr + (size_t)(kb + r) * KV_DIM + d);
            sm.KVs[r][d + 0] = k4.x; sm.KVs[r][d + 1] = k4.y;
            sm.KVs[r][d + 2] = k4.z; sm.KVs[r][d + 3] = k4.w;
        }
        __syncthreads();

        float s[4][4] = {};
        #pragma unroll 4
        for (int d = 0; d < 64; ++d) {
            float qf[4], kf[4];
            #pragma unroll
            for (int i = 0; i < 4; i++) qf[i] = sm.Qs[r0 + i][d];
            #pragma unroll
            for (int j = 0; j < 4; j++) kf[j] = sm.KVs[c0 + j][d];
            #pragma unroll
            for (int i = 0; i < 4; i++)
                #pragma unroll
                for (int j = 0; j < 4; j++) s[i][j] += qf[i] * kf[j];
        }
        #pragma unroll
        for (int i = 0; i < 4; i++)
            #pragma unroll
            for (int j = 0; j < 4; j++) s[i][j] *= 0.125f;

        __syncthreads();

        #pragma unroll
        for (int i = 0; i < 4; i++) {
            float mx = fmaxf(fmaxf(s[i][0], s[i][1]), fmaxf(s[i][2], s[i][3]));
            sm.red[r0 + i][tx] = mx;
        }
        __syncthreads();

        if (t < 64) {
            float mx = sm.red[t][0];
            #pragma unroll
            for (int jj = 1; jj < 16; jj++) mx = fmaxf(mx, sm.red[t][jj]);
            float mo = sm.m_run[t];
            float mn = fmaxf(mo, mx);
            sm.m_cur[t]  = mn;
            sm.alpha[t]  = expf(mo - mn);
            sm.m_run[t]  = mn;
        }
        __syncthreads();

        #pragma unroll
        for (int i = 0; i < 4; i++) {
            float mn = sm.m_cur[r0 + i];
            float ps = 0.f;
            #pragma unroll
            for (int j = 0; j < 4; j++) {
                float p = expf(s[i][j] - mn);
                sm.Ps[r0 + i][c0 + j] = p;
                ps += p;
            }
            sm.red[r0 + i][tx] = ps;
        }
        #pragma unroll
        for (int i = 0; i < 4; i++) {
            int vi = t + i * 256;
            int r  = vi >> 4;
            int d  = (vi & 15) * 4;
            float4 v4 = *reinterpret_cast<const float4*>(vptr + (size_t)(kb + r) * KV_DIM + d);
            sm.KVs[r][d + 0] = v4.x; sm.KVs[r][d + 1] = v4.y;
            sm.KVs[r][d + 2] = v4.z; sm.KVs[r][d + 3] = v4.w;
        }
        __syncthreads();

        if (t < 64) {
            float su = 0.f;
            #pragma unroll
            for (int jj = 0; jj < 16; jj++) su += sm.red[t][jj];
            sm.l_run[t] = sm.alpha[t] * sm.l_run[t] + su;
        }

        #pragma unroll
        for (int i = 0; i < 4; i++) {
            float a = sm.alpha[r0 + i];
            #pragma unroll
            for (int j = 0; j < 4; j++) o[i][j] *= a;
        }
        #pragma unroll 4
        for (int kk = 0; kk < 64; ++kk) {
            float pf[4], vf[4];
            #pragma unroll
            for (int i = 0; i < 4; i++) pf[i] = sm.Ps[r0 + i][kk];
            #pragma unroll
            for (int j = 0; j < 4; j++) vf[j] = sm.KVs[kk][c0 + j];
            #pragma unroll
            for (int i = 0; i < 4; i++)
                #pragma unroll
                for (int j = 0; j < 4; j++) o[i][j] += pf[i] * vf[j];
        }
        __syncthreads();
    }

    #pragma unroll
    for (int i = 0; i < 4; i++) {
        float inv = 1.0f / sm.l_run[r0 + i];
        float4 o4 = make_float4(o[i][0] * inv, o[i][1] * inv, o[i][2] * inv, o[i][3] * inv);
        float* dst = out + ((size_t)b * SEQ + qb + r0 + i) * C_DIM + h * DH + c0;
        *reinterpret_cast<float4*>(dst) = o4;
    }
}

// ---------------------------------------------------------------------------
// Launch
// ---------------------------------------------------------------------------
extern "C" void kernel_launch(void* const* d_in, const int* in_sizes, int n_in,
                              void* d_out, int out_size)
{
    const float* x       = (const float*)d_in[0];
    const float* q_extra = (const float*)d_in[1];
    const float* ln1_g   = (const float*)d_in[2];
    const float* ln1_b   = (const float*)d_in[3];
    const float* w_kv    = (const float*)d_in[4];
    const float* w_out   = (const float*)d_in[5];
    const float* b_out   = (const float*)d_in[6];
    const float* ln2_g   = (const float*)d_in[7];
    const float* ln2_b   = (const float*)d_in[8];
    const float* w1      = (const float*)d_in[9];
    const float* b1      = (const float*)d_in[10];
    const float* w2      = (const float*)d_in[11];
    const float* b2      = (const float*)d_in[12];
    float* out = (float*)d_out;

    float *xn, *kvp, *att, *x2, *h, *hh;
    cudaGetSymbolAddress((void**)&xn,  g_xn);
    cudaGetSymbolAddress((void**)&kvp, g_kv);
    cudaGetSymbolAddress((void**)&att, g_att);
    cudaGetSymbolAddress((void**)&x2,  g_x2);
    cudaGetSymbolAddress((void**)&h,   g_h);
    cudaGetSymbolAddress((void**)&hh,  g_hh);

    float *wkv_hi, *wkv_lo, *wout_hi, *wout_lo, *w1_hi, *w1_lo, *w2_hi, *w2_lo;
    cudaGetSymbolAddress((void**)&wkv_hi,  g_wkv_hi);
    cudaGetSymbolAddress((void**)&wkv_lo,  g_wkv_lo);
    cudaGetSymbolAddress((void**)&wout_hi, g_wout_hi);
    cudaGetSymbolAddress((void**)&wout_lo, g_wout_lo);
    cudaGetSymbolAddress((void**)&w1_hi,   g_w1_hi);
    cudaGetSymbolAddress((void**)&w1_lo,   g_w1_lo);
    cudaGetSymbolAddress((void**)&w2_hi,   g_w2_hi);
    cudaGetSymbolAddress((void**)&w2_lo,   g_w2_lo);

    cudaFuncSetAttribute(attn_kernel, cudaFuncAttributeMaxDynamicSharedMemorySize,
                         (int)sizeof(AttSmem));

    // 0) Pre-split weights to tf32 hi/lo
    {
        int n;
        n = C_DIM * KV_DIM; split_tf32_kernel<<<(n + 255) / 256, 256>>>(w_kv, wkv_hi, wkv_lo, n);
        n = C_DIM * C_DIM;  split_tf32_kernel<<<(n + 255) / 256, 256>>>(w_out, wout_hi, wout_lo, n);
        n = C_DIM * HID;    split_tf32_kernel<<<(n + 255) / 256, 256>>>(w1, w1_hi, w1_lo, n);
        n = HID * C_DIM;    split_tf32_kernel<<<(n + 255) / 256, 256>>>(w2, w2_hi, w2_lo, n);
    }

    // 1) xn = LN1(x)
    ln_kernel<<<TOKENS, 256>>>(x, ln1_g, ln1_b, xn);

    // 2) kv = xn @ w_kv                     [8192 x 1536, K=768]
    tgemm<EPI_NONE><<<dim3(KV_DIM / 128, TOKENS / 128), 256>>>(
        TOKENS, KV_DIM, C_DIM, xn, wkv_hi, wkv_lo, nullptr, nullptr, kvp);

    // 3) att = softmax(q k^T / sqrt(dh)) v
    attn_kernel<<<dim3(SEQ / 64, HEADS, BATCH), 256, sizeof(AttSmem)>>>(q_extra, kvp, att);

    // 4) x2 = x + att @ w_out + b_out       [8192 x 768, K=768]
    tgemm<EPI_BIAS_RES><<<dim3(C_DIM / 128, TOKENS / 128), 256>>>(
        TOKENS, C_DIM, C_DIM, att, wout_hi, wout_lo, b_out, x, x2);

    // 5) h = LN2(x2)
    ln_kernel<<<TOKENS, 256>>>(x2, ln2_g, ln2_b, h);

    // 6) hh = gelu(h @ w1 + b1)             [8192 x 3072, K=768]
    tgemm<EPI_BIAS_GELU><<<dim3(HID / 128, TOKENS / 128), 256>>>(
        TOKENS, HID, C_DIM, h, w1_hi, w1_lo, b1, nullptr, hh);

    // 7) out = x2 + hh @ w2 + b2            [8192 x 768, K=3072]
    tgemm<EPI_BIAS_RES><<<dim3(C_DIM / 128, TOKENS / 128), 256>>>(
        TOKENS, C_DIM, HID, hh, w2_hi, w2_lo, b2, x2, out);
}

// round 9
// speedup vs baseline: 1.8919x; 1.5347x over previous
#include <cuda_runtime.h>
#include <cuda_bf16.h>
#include <math.h>
#include <stdint.h>

// Problem constants
#define TOKENS 8192      // B*N = 8*1024
#define BATCH  8
#define SEQ    1024
#define C_DIM  768
#define KV_DIM 1536
#define HID    3072
#define HEADS  12
#define DH     64

// ---------------------------------------------------------------------------
// Scratch (device globals; no runtime allocation)
// ---------------------------------------------------------------------------
__device__ __nv_bfloat16 g_xn_h [TOKENS * C_DIM];
__device__ __nv_bfloat16 g_xn_l [TOKENS * C_DIM];
__device__ float         g_kv   [TOKENS * KV_DIM];
__device__ __nv_bfloat16 g_att_h[TOKENS * C_DIM];
__device__ __nv_bfloat16 g_att_l[TOKENS * C_DIM];
__device__ float         g_x2   [TOKENS * C_DIM];
__device__ __nv_bfloat16 g_h_h  [TOKENS * C_DIM];
__device__ __nv_bfloat16 g_h_l  [TOKENS * C_DIM];
__device__ __nv_bfloat16 g_hh_h [TOKENS * HID];
__device__ __nv_bfloat16 g_hh_l [TOKENS * HID];

// Transposed + bf16-split weights: [N, K] row-major (i.e. W^T)
__device__ __nv_bfloat16 g_wkv_h [KV_DIM * C_DIM];
__device__ __nv_bfloat16 g_wkv_l [KV_DIM * C_DIM];
__device__ __nv_bfloat16 g_wout_h[C_DIM * C_DIM];
__device__ __nv_bfloat16 g_wout_l[C_DIM * C_DIM];
__device__ __nv_bfloat16 g_w1_h  [HID * C_DIM];
__device__ __nv_bfloat16 g_w1_l  [HID * C_DIM];
__device__ __nv_bfloat16 g_w2_h  [C_DIM * HID];
__device__ __nv_bfloat16 g_w2_l  [C_DIM * HID];

// ---------------------------------------------------------------------------
// Helpers
// ---------------------------------------------------------------------------
__device__ __forceinline__ void bsplit(float v, __nv_bfloat16& h, __nv_bfloat16& l) {
    h = __float2bfloat16(v);
    l = __float2bfloat16(v - __bfloat162float(h));
}

// bf16 m16n8k16 MMA (row.col), fp32 accumulate — supported on plain sm_103
__device__ __forceinline__ void mma_bf16(float* c, const uint32_t* a,
                                         uint32_t b0, uint32_t b1) {
    asm volatile(
        "mma.sync.aligned.m16n8k16.row.col.f32.bf16.bf16.f32 "
        "{%0,%1,%2,%3}, {%4,%5,%6,%7}, {%8,%9}, {%0,%1,%2,%3};"
        : "+f"(c[0]), "+f"(c[1]), "+f"(c[2]), "+f"(c[3])
        : "r"(a[0]), "r"(a[1]), "r"(a[2]), "r"(a[3]), "r"(b0), "r"(b1));
}

#define CP_ASYNC16(smem_u32, gptr) \
    asm volatile("cp.async.cg.shared.global [%0], [%1], 16;" \
        :: "r"(smem_u32), "l"(gptr) : "memory")
#define CP_COMMIT() asm volatile("cp.async.commit_group;" ::: "memory")
#define CP_WAIT1()  asm volatile("cp.async.wait_group 1;" ::: "memory")
#define CP_WAIT0()  asm volatile("cp.async.wait_group 0;" ::: "memory")

// ---------------------------------------------------------------------------
// Weight transpose + bf16 split: w[K,N] fp32 -> th/tl[N,K] bf16
// ---------------------------------------------------------------------------
__global__ void __launch_bounds__(256) wsplit_t(
    const float* __restrict__ w, __nv_bfloat16* __restrict__ th,
    __nv_bfloat16* __restrict__ tl, int K, int N)
{
    __shared__ float tile[32][33];
    const int n0 = blockIdx.x * 32, k0 = blockIdx.y * 32;
    const int tx = threadIdx.x, ty = threadIdx.y;
    #pragma unroll
    for (int i = ty; i < 32; i += 8)
        tile[i][tx] = w[(size_t)(k0 + i) * N + n0 + tx];
    __syncthreads();
    #pragma unroll
    for (int i = ty; i < 32; i += 8) {
        float v = tile[tx][i];                 // = w[k0+tx][n0+i]
        __nv_bfloat16 h, l; bsplit(v, h, l);
        size_t o = (size_t)(n0 + i) * K + k0 + tx;
        th[o] = h; tl[o] = l;
    }
}

// ---------------------------------------------------------------------------
// LayerNorm -> bf16 hi/lo outputs
// ---------------------------------------------------------------------------
__global__ void __launch_bounds__(256) ln_kernel(
    const float* __restrict__ x, const float* __restrict__ g,
    const float* __restrict__ b,
    __nv_bfloat16* __restrict__ hi, __nv_bfloat16* __restrict__ lo)
{
    __shared__ float sh[9];
    const int row = blockIdx.x;
    const int t = threadIdx.x;
    const float* xr = x + (size_t)row * C_DIM;

    float v0 = xr[t], v1 = xr[t + 256], v2 = xr[t + 512];

    float s = v0 + v1 + v2;
    #pragma unroll
    for (int o = 16; o; o >>= 1) s += __shfl_xor_sync(0xffffffffu, s, o);
    if ((t & 31) == 0) sh[t >> 5] = s;
    __syncthreads();
    if (t == 0) {
        float a = 0.f;
        #pragma unroll
        for (int i = 0; i < 8; i++) a += sh[i];
        sh[8] = a * (1.0f / C_DIM);
    }
    __syncthreads();
    const float mu = sh[8];

    float d0 = v0 - mu, d1 = v1 - mu, d2 = v2 - mu;
    float q = d0 * d0 + d1 * d1 + d2 * d2;
    __syncthreads();
    #pragma unroll
    for (int o = 16; o; o >>= 1) q += __shfl_xor_sync(0xffffffffu, q, o);
    if ((t & 31) == 0) sh[t >> 5] = q;
    __syncthreads();
    if (t == 0) {
        float a = 0.f;
        #pragma unroll
        for (int i = 0; i < 8; i++) a += sh[i];
        sh[8] = rsqrtf(a * (1.0f / C_DIM) + 1e-5f);
    }
    __syncthreads();
    const float rs = sh[8];

    const size_t rb = (size_t)row * C_DIM;
    float vals[3] = { d0 * rs * g[t] + b[t],
                      d1 * rs * g[t + 256] + b[t + 256],
                      d2 * rs * g[t + 512] + b[t + 512] };
    #pragma unroll
    for (int i = 0; i < 3; i++) {
        __nv_bfloat16 h, l; bsplit(vals[i], h, l);
        hi[rb + t + i * 256] = h;
        lo[rb + t + i * 256] = l;
    }
}

// ---------------------------------------------------------------------------
// bf16x3 tensor-core GEMM: C[M,N] = A @ Bt^T (+bias)(+resid | GELU)
// A: bf16 hi/lo [M,K] row-major; Bt: bf16 hi/lo [N,K] row-major.
// mma.m16n8k16 bf16, fp32 accum. Block tile 128x128, BK=32, 256 thr, 8 warps
// (2x4, warp tile 64x32). cp.async double-buffered smem, stride-40 layout
// (bank = (20g+ti)%32 — conflict-free fragment reads).
// ---------------------------------------------------------------------------
enum { EPI_NONE = 0, EPI_BIAS_RES = 1, EPI_BIAS_GELU = 2 };
enum { OUT_F32 = 0, OUT_BF16 = 1 };

#define BK 32
#define ST 40                       // smem row stride in bf16 elems
#define ARR_ELEMS (128 * ST)        // 5120 bf16 = 10240 B per array
#define STAGE_ELEMS (4 * ARR_ELEMS) // Ah, Al, Bh, Bl
#define TG_SMEM (2 * STAGE_ELEMS * 2)  // bytes = 81920

template <int EPI, int OUTM>
__global__ void __launch_bounds__(256) tgemm_bf3(
    int M, int N, int K,
    const __nv_bfloat16* __restrict__ Ahi, const __nv_bfloat16* __restrict__ Alo,
    const __nv_bfloat16* __restrict__ Bth, const __nv_bfloat16* __restrict__ Btl,
    const float* __restrict__ bias, const float* __restrict__ resid,
    float* __restrict__ C,
    __nv_bfloat16* __restrict__ Chi, __nv_bfloat16* __restrict__ Clo)
{
    extern __shared__ __nv_bfloat16 smem[];
    const uint32_t smb = (uint32_t)__cvta_generic_to_shared(smem);

    const int t    = threadIdx.x;
    const int lane = t & 31;
    const int warp = t >> 5;
    const int wm   = (warp >> 2) * 64;   // 0 or 64
    const int wn   = (warp & 3) * 32;    // 0,32,64,96
    const int g    = lane >> 2;          // 0..7
    const int ti   = lane & 3;           // 0..3

    const __nv_bfloat16* Ab_h = Ahi + (size_t)blockIdx.y * 128 * K;
    const __nv_bfloat16* Ab_l = Alo + (size_t)blockIdx.y * 128 * K;
    const __nv_bfloat16* Bb_h = Bth + (size_t)blockIdx.x * 128 * K;
    const __nv_bfloat16* Bb_l = Btl + (size_t)blockIdx.x * 128 * K;
    const __nv_bfloat16* srcs[4] = { Ab_h, Ab_l, Bb_h, Bb_l };

    // loader: per array 128 rows x 32 cols bf16 = 512 uint4; 2 per thread
    const int r0l = (t) >> 2,        q0l = (t) & 3;
    const int r1l = (t + 256) >> 2,  q1l = (t + 256) & 3;

    auto issue = [&](int c) {
        const int s = c & 1;
        const uint32_t sb = smb + s * (STAGE_ELEMS * 2);
        #pragma unroll
        for (int arr = 0; arr < 4; ++arr) {
            const __nv_bfloat16* src = srcs[arr] + c * BK;
            const uint32_t db = sb + arr * (ARR_ELEMS * 2);
            CP_ASYNC16(db + (uint32_t)(r0l * (ST * 2) + q0l * 16),
                       src + (size_t)r0l * K + q0l * 8);
            CP_ASYNC16(db + (uint32_t)(r1l * (ST * 2) + q1l * 16),
                       src + (size_t)r1l * K + q1l * 8);
        }
        CP_COMMIT();
    };

    float acc[4][4][4];
    #pragma unroll
    for (int i = 0; i < 4; i++)
        #pragma unroll
        for (int j = 0; j < 4; j++)
            #pragma unroll
            for (int k = 0; k < 4; k++) acc[i][j][k] = 0.f;

    const int nStages = K / BK;
    issue(0);
    if (nStages > 1) issue(1);

    for (int c = 0; c < nStages; ++c) {
        if (c + 1 < nStages) { CP_WAIT1(); } else { CP_WAIT0(); }
        __syncthreads();

        const int s = c & 1;
        const __nv_bfloat16* sAh = smem + s * STAGE_ELEMS;
        const __nv_bfloat16* sAl = sAh + ARR_ELEMS;
        const __nv_bfloat16* sBh = sAl + ARR_ELEMS;
        const __nv_bfloat16* sBl = sBh + ARR_ELEMS;

        #pragma unroll
        for (int ks = 0; ks < BK; ks += 16) {
            uint32_t ah[4][4], al[4][4];
            #pragma unroll
            for (int ib = 0; ib < 4; ++ib) {
                const int rb = (wm + ib * 16 + g) * ST + ks + 2 * ti;
                ah[ib][0] = *reinterpret_cast<const uint32_t*>(sAh + rb);
                ah[ib][1] = *reinterpret_cast<const uint32_t*>(sAh + rb + 8 * ST);
                ah[ib][2] = *reinterpret_cast<const uint32_t*>(sAh + rb + 8);
                ah[ib][3] = *reinterpret_cast<const uint32_t*>(sAh + rb + 8 * ST + 8);
                al[ib][0] = *reinterpret_cast<const uint32_t*>(sAl + rb);
                al[ib][1] = *reinterpret_cast<const uint32_t*>(sAl + rb + 8 * ST);
                al[ib][2] = *reinterpret_cast<const uint32_t*>(sAl + rb + 8);
                al[ib][3] = *reinterpret_cast<const uint32_t*>(sAl + rb + 8 * ST + 8);
            }
            #pragma unroll
            for (int jb = 0; jb < 4; ++jb) {
                const int nb = (wn + jb * 8 + g) * ST + ks + 2 * ti;
                const uint32_t bh0 = *reinterpret_cast<const uint32_t*>(sBh + nb);
                const uint32_t bh1 = *reinterpret_cast<const uint32_t*>(sBh + nb + 8);
                const uint32_t bl0 = *reinterpret_cast<const uint32_t*>(sBl + nb);
                const uint32_t bl1 = *reinterpret_cast<const uint32_t*>(sBl + nb + 8);
                #pragma unroll
                for (int ib = 0; ib < 4; ++ib) {
                    mma_bf16(acc[ib][jb], ah[ib], bh0, bh1);   // hi*hi
                    mma_bf16(acc[ib][jb], ah[ib], bl0, bl1);   // hi*lo
                    mma_bf16(acc[ib][jb], al[ib], bh0, bh1);   // lo*hi
                }
            }
        }
        __syncthreads();
        if (c + 2 < nStages) issue(c + 2);
    }

    // Epilogue: c0,c1 at (g, 2ti/(+1)); c2,c3 at (g+8, ...)
    const int row0 = blockIdx.y * 128 + wm;
    const int col0 = blockIdx.x * 128 + wn;
    #pragma unroll
    for (int ib = 0; ib < 4; ++ib) {
        #pragma unroll
        for (int jb = 0; jb < 4; ++jb) {
            const int cc = col0 + jb * 8 + 2 * ti;
            #pragma unroll
            for (int half = 0; half < 2; half++) {
                const int r = row0 + ib * 16 + g + half * 8;
                float e0 = acc[ib][jb][half * 2 + 0];
                float e1 = acc[ib][jb][half * 2 + 1];
                const size_t off = (size_t)r * N + cc;
                if (EPI != EPI_NONE) {
                    e0 += bias[cc];
                    e1 += bias[cc + 1];
                }
                if (EPI == EPI_BIAS_RES) {
                    float2 rr = *reinterpret_cast<const float2*>(resid + off);
                    e0 += rr.x;
                    e1 += rr.y;
                }
                if (EPI == EPI_BIAS_GELU) {
                    e0 = 0.5f * e0 * (1.0f + erff(e0 * 0.70710678118654752f));
                    e1 = 0.5f * e1 * (1.0f + erff(e1 * 0.70710678118654752f));
                }
                if (OUTM == OUT_F32) {
                    *reinterpret_cast<float2*>(C + off) = make_float2(e0, e1);
                } else {
                    __nv_bfloat162 hh2, ll2;
                    bsplit(e0, hh2.x, ll2.x);
                    bsplit(e1, hh2.y, ll2.y);
                    *reinterpret_cast<__nv_bfloat162*>(Chi + off) = hh2;
                    *reinterpret_cast<__nv_bfloat162*>(Clo + off) = ll2;
                }
            }
        }
    }
}

// ---------------------------------------------------------------------------
// Flash attention, fp32; epilogue emits bf16 hi/lo for the out-proj GEMM.
// ---------------------------------------------------------------------------
struct AttSmem {
    float Qs [64][65];
    float KVs[64][65];
    float Ps [64][65];
    float red[64][16];
    float m_run[64];
    float l_run[64];
    float alpha[64];
    float m_cur[64];
};

__global__ void __launch_bounds__(256) attn_kernel(
    const float* __restrict__ qx, const float* __restrict__ kv,
    __nv_bfloat16* __restrict__ out_h, __nv_bfloat16* __restrict__ out_l)
{
    extern __shared__ unsigned char smem_raw[];
    AttSmem& sm = *reinterpret_cast<AttSmem*>(smem_raw);

    const int t  = threadIdx.x;
    const int tx = t & 15, ty = t >> 4;
    const int r0 = ty * 4, c0 = tx * 4;
    const int qb = blockIdx.x * 64;
    const int h  = blockIdx.y;
    const int b  = blockIdx.z;

    const float* qptr = qx + ((size_t)b * SEQ) * C_DIM  + (size_t)h * DH;
    const float* kptr = kv + ((size_t)b * SEQ) * KV_DIM + (size_t)h * DH;
    const float* vptr = kptr + C_DIM;

    #pragma unroll
    for (int i = 0; i < 4; i++) {
        int vi = t + i * 256;
        int r  = vi >> 4;
        int d  = (vi & 15) * 4;
        float4 q4 = *reinterpret_cast<const float4*>(qptr + (size_t)(qb + r) * C_DIM + d);
        sm.Qs[r][d + 0] = q4.x; sm.Qs[r][d + 1] = q4.y;
        sm.Qs[r][d + 2] = q4.z; sm.Qs[r][d + 3] = q4.w;
    }
    if (t < 64) { sm.m_run[t] = -INFINITY; sm.l_run[t] = 0.f; }

    float o[4][4] = {};
    __syncthreads();

    for (int kt = 0; kt < 16; ++kt) {
        const int kb = kt * 64;

        #pragma unroll
        for (int i = 0; i < 4; i++) {
            int vi = t + i * 256;
            int r  = vi >> 4;
            int d  = (vi & 15) * 4;
            float4 k4 = *reinterpret_cast<const float4*>(kptr + (size_t)(kb + r) * KV_DIM + d);
            sm.KVs[r][d + 0] = k4.x; sm.KVs[r][d + 1] = k4.y;
            sm.KVs[r][d + 2] = k4.z; sm.KVs[r][d + 3] = k4.w;
        }
        __syncthreads();

        float s[4][4] = {};
        #pragma unroll 4
        for (int d = 0; d < 64; ++d) {
            float qf[4], kf[4];
            #pragma unroll
            for (int i = 0; i < 4; i++) qf[i] = sm.Qs[r0 + i][d];
            #pragma unroll
            for (int j = 0; j < 4; j++) kf[j] = sm.KVs[c0 + j][d];
            #pragma unroll
            for (int i = 0; i < 4; i++)
                #pragma unroll
                for (int j = 0; j < 4; j++) s[i][j] += qf[i] * kf[j];
        }
        #pragma unroll
        for (int i = 0; i < 4; i++)
            #pragma unroll
            for (int j = 0; j < 4; j++) s[i][j] *= 0.125f;

        __syncthreads();

        #pragma unroll
        for (int i = 0; i < 4; i++) {
            float mx = fmaxf(fmaxf(s[i][0], s[i][1]), fmaxf(s[i][2], s[i][3]));
            sm.red[r0 + i][tx] = mx;
        }
        __syncthreads();

        if (t < 64) {
            float mx = sm.red[t][0];
            #pragma unroll
            for (int jj = 1; jj < 16; jj++) mx = fmaxf(mx, sm.red[t][jj]);
            float mo = sm.m_run[t];
            float mn = fmaxf(mo, mx);
            sm.m_cur[t]  = mn;
            sm.alpha[t]  = expf(mo - mn);
            sm.m_run[t]  = mn;
        }
        __syncthreads();

        #pragma unroll
        for (int i = 0; i < 4; i++) {
            float mn = sm.m_cur[r0 + i];
            float ps = 0.f;
            #pragma unroll
            for (int j = 0; j < 4; j++) {
                float p = expf(s[i][j] - mn);
                sm.Ps[r0 + i][c0 + j] = p;
                ps += p;
            }
            sm.red[r0 + i][tx] = ps;
        }
        #pragma unroll
        for (int i = 0; i < 4; i++) {
            int vi = t + i * 256;
            int r  = vi >> 4;
            int d  = (vi & 15) * 4;
            float4 v4 = *reinterpret_cast<const float4*>(vptr + (size_t)(kb + r) * KV_DIM + d);
            sm.KVs[r][d + 0] = v4.x; sm.KVs[r][d + 1] = v4.y;
            sm.KVs[r][d + 2] = v4.z; sm.KVs[r][d + 3] = v4.w;
        }
        __syncthreads();

        if (t < 64) {
            float su = 0.f;
            #pragma unroll
            for (int jj = 0; jj < 16; jj++) su += sm.red[t][jj];
            sm.l_run[t] = sm.alpha[t] * sm.l_run[t] + su;
        }

        #pragma unroll
        for (int i = 0; i < 4; i++) {
            float a = sm.alpha[r0 + i];
            #pragma unroll
            for (int j = 0; j < 4; j++) o[i][j] *= a;
        }
        #pragma unroll 4
        for (int kk = 0; kk < 64; ++kk) {
            float pf[4], vf[4];
            #pragma unroll
            for (int i = 0; i < 4; i++) pf[i] = sm.Ps[r0 + i][kk];
            #pragma unroll
            for (int j = 0; j < 4; j++) vf[j] = sm.KVs[kk][c0 + j];
            #pragma unroll
            for (int i = 0; i < 4; i++)
                #pragma unroll
                for (int j = 0; j < 4; j++) o[i][j] += pf[i] * vf[j];
        }
        __syncthreads();
    }

    #pragma unroll
    for (int i = 0; i < 4; i++) {
        float inv = 1.0f / sm.l_run[r0 + i];
        const size_t off = ((size_t)b * SEQ + qb + r0 + i) * C_DIM + h * DH + c0;
        __nv_bfloat162 h01, h23, l01, l23;
        bsplit(o[i][0] * inv, h01.x, l01.x);
        bsplit(o[i][1] * inv, h01.y, l01.y);
        bsplit(o[i][2] * inv, h23.x, l23.x);
        bsplit(o[i][3] * inv, h23.y, l23.y);
        *reinterpret_cast<__nv_bfloat162*>(out_h + off)     = h01;
        *reinterpret_cast<__nv_bfloat162*>(out_h + off + 2) = h23;
        *reinterpret_cast<__nv_bfloat162*>(out_l + off)     = l01;
        *reinterpret_cast<__nv_bfloat162*>(out_l + off + 2) = l23;
    }
}

// ---------------------------------------------------------------------------
// Launch
// ---------------------------------------------------------------------------
extern "C" void kernel_launch(void* const* d_in, const int* in_sizes, int n_in,
                              void* d_out, int out_size)
{
    const float* x       = (const float*)d_in[0];
    const float* q_extra = (const float*)d_in[1];
    const float* ln1_g   = (const float*)d_in[2];
    const float* ln1_b   = (const float*)d_in[3];
    const float* w_kv    = (const float*)d_in[4];
    const float* w_out   = (const float*)d_in[5];
    const float* b_out   = (const float*)d_in[6];
    const float* ln2_g   = (const float*)d_in[7];
    const float* ln2_b   = (const float*)d_in[8];
    const float* w1      = (const float*)d_in[9];
    const float* b1      = (const float*)d_in[10];
    const float* w2      = (const float*)d_in[11];
    const float* b2      = (const float*)d_in[12];
    float* out = (float*)d_out;

    __nv_bfloat16 *xn_h, *xn_l, *att_h, *att_l, *h_h, *h_l, *hh_h, *hh_l;
    __nv_bfloat16 *wkv_h, *wkv_l, *wout_h, *wout_l, *w1_h, *w1_l, *w2_h, *w2_l;
    float *kvp, *x2;
    cudaGetSymbolAddress((void**)&xn_h,  g_xn_h);  cudaGetSymbolAddress((void**)&xn_l,  g_xn_l);
    cudaGetSymbolAddress((void**)&att_h, g_att_h); cudaGetSymbolAddress((void**)&att_l, g_att_l);
    cudaGetSymbolAddress((void**)&h_h,   g_h_h);   cudaGetSymbolAddress((void**)&h_l,   g_h_l);
    cudaGetSymbolAddress((void**)&hh_h,  g_hh_h);  cudaGetSymbolAddress((void**)&hh_l,  g_hh_l);
    cudaGetSymbolAddress((void**)&wkv_h, g_wkv_h); cudaGetSymbolAddress((void**)&wkv_l, g_wkv_l);
    cudaGetSymbolAddress((void**)&wout_h,g_wout_h);cudaGetSymbolAddress((void**)&wout_l,g_wout_l);
    cudaGetSymbolAddress((void**)&w1_h,  g_w1_h);  cudaGetSymbolAddress((void**)&w1_l,  g_w1_l);
    cudaGetSymbolAddress((void**)&w2_h,  g_w2_h);  cudaGetSymbolAddress((void**)&w2_l,  g_w2_l);
    cudaGetSymbolAddress((void**)&kvp,   g_kv);
    cudaGetSymbolAddress((void**)&x2,    g_x2);

    cudaFuncSetAttribute(attn_kernel, cudaFuncAttributeMaxDynamicSharedMemorySize,
                         (int)sizeof(AttSmem));
    cudaFuncSetAttribute(tgemm_bf3<EPI_NONE, OUT_F32>,
                         cudaFuncAttributeMaxDynamicSharedMemorySize, TG_SMEM);
    cudaFuncSetAttribute(tgemm_bf3<EPI_BIAS_RES, OUT_F32>,
                         cudaFuncAttributeMaxDynamicSharedMemorySize, TG_SMEM);
    cudaFuncSetAttribute(tgemm_bf3<EPI_BIAS_GELU, OUT_BF16>,
                         cudaFuncAttributeMaxDynamicSharedMemorySize, TG_SMEM);

    // 0) Weight transpose + bf16 split: [K,N] -> [N,K] hi/lo
    wsplit_t<<<dim3(KV_DIM / 32, C_DIM / 32), dim3(32, 8)>>>(w_kv,  wkv_h,  wkv_l,  C_DIM, KV_DIM);
    wsplit_t<<<dim3(C_DIM / 32,  C_DIM / 32), dim3(32, 8)>>>(w_out, wout_h, wout_l, C_DIM, C_DIM);
    wsplit_t<<<dim3(HID / 32,    C_DIM / 32), dim3(32, 8)>>>(w1,    w1_h,   w1_l,   C_DIM, HID);
    wsplit_t<<<dim3(C_DIM / 32,  HID / 32),   dim3(32, 8)>>>(w2,    w2_h,   w2_l,   HID,   C_DIM);

    // 1) xn = LN1(x)  (bf16 hi/lo)
    ln_kernel<<<TOKENS, 256>>>(x, ln1_g, ln1_b, xn_h, xn_l);

    // 2) kv = xn @ w_kv            [8192 x 1536, K=768]
    tgemm_bf3<EPI_NONE, OUT_F32><<<dim3(KV_DIM / 128, TOKENS / 128), 256, TG_SMEM>>>(
        TOKENS, KV_DIM, C_DIM, xn_h, xn_l, wkv_h, wkv_l,
        nullptr, nullptr, kvp, nullptr, nullptr);

    // 3) att = softmax(q k^T / 8) v   (bf16 hi/lo)
    attn_kernel<<<dim3(SEQ / 64, HEADS, BATCH), 256, sizeof(AttSmem)>>>(
        q_extra, kvp, att_h, att_l);

    // 4) x2 = x + att @ w_out + b_out   [8192 x 768, K=768]
    tgemm_bf3<EPI_BIAS_RES, OUT_F32><<<dim3(C_DIM / 128, TOKENS / 128), 256, TG_SMEM>>>(
        TOKENS, C_DIM, C_DIM, att_h, att_l, wout_h, wout_l,
        b_out, x, x2, nullptr, nullptr);

    // 5) h = LN2(x2)   (bf16 hi/lo)
    ln_kernel<<<TOKENS, 256>>>(x2, ln2_g, ln2_b, h_h, h_l);

    // 6) hh = gelu(h @ w1 + b1)   [8192 x 3072, K=768] (bf16 hi/lo)
    tgemm_bf3<EPI_BIAS_GELU, OUT_BF16><<<dim3(HID / 128, TOKENS / 128), 256, TG_SMEM>>>(
        TOKENS, HID, C_DIM, h_h, h_l, w1_h, w1_l,
        b1, nullptr, nullptr, hh_h, hh_l);

    // 7) out = x2 + hh @ w2 + b2   [8192 x 768, K=3072]
    tgemm_bf3<EPI_BIAS_RES, OUT_F32><<<dim3(C_DIM / 128, TOKENS / 128), 256, TG_SMEM>>>(
        TOKENS, C_DIM, HID, hh_h, hh_l, w2_h, w2_l,
        b2, x2, out, nullptr, nullptr);
}

// round 10
// speedup vs baseline: 1.8924x; 1.0002x over previous
#include <cuda_runtime.h>
#include <cuda_bf16.h>
#include <math.h>
#include <stdint.h>

// Problem constants
#define TOKENS 8192      // B*N = 8*1024
#define BATCH  8
#define SEQ    1024
#define C_DIM  768
#define KV_DIM 1536
#define HID    3072
#define HEADS  12
#define DH     64

// ---------------------------------------------------------------------------
// Scratch (device globals; no runtime allocation)
// ---------------------------------------------------------------------------
__device__ __nv_bfloat16 g_xn_h [TOKENS * C_DIM];
__device__ __nv_bfloat16 g_xn_l [TOKENS * C_DIM];
__device__ float         g_kv   [TOKENS * KV_DIM];
__device__ __nv_bfloat16 g_att_h[TOKENS * C_DIM];
__device__ __nv_bfloat16 g_att_l[TOKENS * C_DIM];
__device__ float         g_x2   [TOKENS * C_DIM];
__device__ __nv_bfloat16 g_h_h  [TOKENS * C_DIM];
__device__ __nv_bfloat16 g_h_l  [TOKENS * C_DIM];
__device__ __nv_bfloat16 g_hh_h [TOKENS * HID];
__device__ __nv_bfloat16 g_hh_l [TOKENS * HID];

// Transposed + bf16-split weights: [N, K] row-major (i.e. W^T)
__device__ __nv_bfloat16 g_wkv_h [KV_DIM * C_DIM];
__device__ __nv_bfloat16 g_wkv_l [KV_DIM * C_DIM];
__device__ __nv_bfloat16 g_wout_h[C_DIM * C_DIM];
__device__ __nv_bfloat16 g_wout_l[C_DIM * C_DIM];
__device__ __nv_bfloat16 g_w1_h  [HID * C_DIM];
__device__ __nv_bfloat16 g_w1_l  [HID * C_DIM];
__device__ __nv_bfloat16 g_w2_h  [C_DIM * HID];
__device__ __nv_bfloat16 g_w2_l  [C_DIM * HID];

// ---------------------------------------------------------------------------
// Helpers
// ---------------------------------------------------------------------------
__device__ __forceinline__ void bsplit(float v, __nv_bfloat16& h, __nv_bfloat16& l) {
    h = __float2bfloat16(v);
    l = __float2bfloat16(v - __bfloat162float(h));
}

// bf16 m16n8k16 MMA (row.col), fp32 accumulate — supported on plain sm_103
__device__ __forceinline__ void mma_bf16(float* c, const uint32_t* a,
                                         uint32_t b0, uint32_t b1) {
    asm volatile(
        "mma.sync.aligned.m16n8k16.row.col.f32.bf16.bf16.f32 "
        "{%0,%1,%2,%3}, {%4,%5,%6,%7}, {%8,%9}, {%0,%1,%2,%3};"
        : "+f"(c[0]), "+f"(c[1]), "+f"(c[2]), "+f"(c[3])
        : "r"(a[0]), "r"(a[1]), "r"(a[2]), "r"(a[3]), "r"(b0), "r"(b1));
}

#define CP_ASYNC16(smem_u32, gptr) \
    asm volatile("cp.async.cg.shared.global [%0], [%1], 16;" \
        :: "r"(smem_u32), "l"(gptr) : "memory")
#define CP_COMMIT() asm volatile("cp.async.commit_group;" ::: "memory")
#define CP_WAIT1()  asm volatile("cp.async.wait_group 1;" ::: "memory")
#define CP_WAIT0()  asm volatile("cp.async.wait_group 0;" ::: "memory")

// ---------------------------------------------------------------------------
// Weight transpose + bf16 split: w[K,N] fp32 -> th/tl[N,K] bf16
// ---------------------------------------------------------------------------
__global__ void __launch_bounds__(256) wsplit_t(
    const float* __restrict__ w, __nv_bfloat16* __restrict__ th,
    __nv_bfloat16* __restrict__ tl, int K, int N)
{
    __shared__ float tile[32][33];
    const int n0 = blockIdx.x * 32, k0 = blockIdx.y * 32;
    const int tx = threadIdx.x, ty = threadIdx.y;
    #pragma unroll
    for (int i = ty; i < 32; i += 8)
        tile[i][tx] = w[(size_t)(k0 + i) * N + n0 + tx];
    __syncthreads();
    #pragma unroll
    for (int i = ty; i < 32; i += 8) {
        float v = tile[tx][i];                 // = w[k0+tx][n0+i]
        __nv_bfloat16 h, l; bsplit(v, h, l);
        size_t o = (size_t)(n0 + i) * K + k0 + tx;
        th[o] = h; tl[o] = l;
    }
}

// ---------------------------------------------------------------------------
// LayerNorm -> bf16 hi/lo outputs
// ---------------------------------------------------------------------------
__global__ void __launch_bounds__(256) ln_kernel(
    const float* __restrict__ x, const float* __restrict__ g,
    const float* __restrict__ b,
    __nv_bfloat16* __restrict__ hi, __nv_bfloat16* __restrict__ lo)
{
    __shared__ float sh[9];
    const int row = blockIdx.x;
    const int t = threadIdx.x;
    const float* xr = x + (size_t)row * C_DIM;

    float v0 = xr[t], v1 = xr[t + 256], v2 = xr[t + 512];

    float s = v0 + v1 + v2;
    #pragma unroll
    for (int o = 16; o; o >>= 1) s += __shfl_xor_sync(0xffffffffu, s, o);
    if ((t & 31) == 0) sh[t >> 5] = s;
    __syncthreads();
    if (t == 0) {
        float a = 0.f;
        #pragma unroll
        for (int i = 0; i < 8; i++) a += sh[i];
        sh[8] = a * (1.0f / C_DIM);
    }
    __syncthreads();
    const float mu = sh[8];

    float d0 = v0 - mu, d1 = v1 - mu, d2 = v2 - mu;
    float q = d0 * d0 + d1 * d1 + d2 * d2;
    __syncthreads();
    #pragma unroll
    for (int o = 16; o; o >>= 1) q += __shfl_xor_sync(0xffffffffu, q, o);
    if ((t & 31) == 0) sh[t >> 5] = q;
    __syncthreads();
    if (t == 0) {
        float a = 0.f;
        #pragma unroll
        for (int i = 0; i < 8; i++) a += sh[i];
        sh[8] = rsqrtf(a * (1.0f / C_DIM) + 1e-5f);
    }
    __syncthreads();
    const float rs = sh[8];

    const size_t rb = (size_t)row * C_DIM;
    float vals[3] = { d0 * rs * g[t] + b[t],
                      d1 * rs * g[t + 256] + b[t + 256],
                      d2 * rs * g[t + 512] + b[t + 512] };
    #pragma unroll
    for (int i = 0; i < 3; i++) {
        __nv_bfloat16 h, l; bsplit(vals[i], h, l);
        hi[rb + t + i * 256] = h;
        lo[rb + t + i * 256] = l;
    }
}

// ---------------------------------------------------------------------------
// bf16x3 tensor-core GEMM: C[M,N] = A @ Bt^T (+bias)(+resid | GELU)
// A: bf16 hi/lo [M,K] row-major; Bt: bf16 hi/lo [N,K] row-major.
// mma.m16n8k16 bf16, fp32 accum. Block tile 128x128, BK=32, 256 thr, 8 warps
// (2x4, warp tile 64x32). cp.async double-buffered smem, stride-40 layout
// (bank = (20g+ti)%32 — conflict-free fragment reads).
// ---------------------------------------------------------------------------
enum { EPI_NONE = 0, EPI_BIAS_RES = 1, EPI_BIAS_GELU = 2 };
enum { OUT_F32 = 0, OUT_BF16 = 1 };

#define BK 32
#define ST 40                       // smem row stride in bf16 elems
#define ARR_ELEMS (128 * ST)        // 5120 bf16 = 10240 B per array
#define STAGE_ELEMS (4 * ARR_ELEMS) // Ah, Al, Bh, Bl
#define TG_SMEM (2 * STAGE_ELEMS * 2)  // bytes = 81920

template <int EPI, int OUTM>
__global__ void __launch_bounds__(256) tgemm_bf3(
    int M, int N, int K,
    const __nv_bfloat16* __restrict__ Ahi, const __nv_bfloat16* __restrict__ Alo,
    const __nv_bfloat16* __restrict__ Bth, const __nv_bfloat16* __restrict__ Btl,
    const float* __restrict__ bias, const float* __restrict__ resid,
    float* __restrict__ C,
    __nv_bfloat16* __restrict__ Chi, __nv_bfloat16* __restrict__ Clo)
{
    extern __shared__ __nv_bfloat16 smem[];
    const uint32_t smb = (uint32_t)__cvta_generic_to_shared(smem);

    const int t    = threadIdx.x;
    const int lane = t & 31;
    const int warp = t >> 5;
    const int wm   = (warp >> 2) * 64;   // 0 or 64
    const int wn   = (warp & 3) * 32;    // 0,32,64,96
    const int g    = lane >> 2;          // 0..7
    const int ti   = lane & 3;           // 0..3

    const __nv_bfloat16* Ab_h = Ahi + (size_t)blockIdx.y * 128 * K;
    const __nv_bfloat16* Ab_l = Alo + (size_t)blockIdx.y * 128 * K;
    const __nv_bfloat16* Bb_h = Bth + (size_t)blockIdx.x * 128 * K;
    const __nv_bfloat16* Bb_l = Btl + (size_t)blockIdx.x * 128 * K;
    const __nv_bfloat16* srcs[4] = { Ab_h, Ab_l, Bb_h, Bb_l };

    // loader: per array 128 rows x 32 cols bf16 = 512 uint4; 2 per thread
    const int r0l = (t) >> 2,        q0l = (t) & 3;
    const int r1l = (t + 256) >> 2,  q1l = (t + 256) & 3;

    auto issue = [&](int c) {
        const int s = c & 1;
        const uint32_t sb = smb + s * (STAGE_ELEMS * 2);
        #pragma unroll
        for (int arr = 0; arr < 4; ++arr) {
            const __nv_bfloat16* src = srcs[arr] + c * BK;
            const uint32_t db = sb + arr * (ARR_ELEMS * 2);
            CP_ASYNC16(db + (uint32_t)(r0l * (ST * 2) + q0l * 16),
                       src + (size_t)r0l * K + q0l * 8);
            CP_ASYNC16(db + (uint32_t)(r1l * (ST * 2) + q1l * 16),
                       src + (size_t)r1l * K + q1l * 8);
        }
        CP_COMMIT();
    };

    float acc[4][4][4];
    #pragma unroll
    for (int i = 0; i < 4; i++)
        #pragma unroll
        for (int j = 0; j < 4; j++)
            #pragma unroll
            for (int k = 0; k < 4; k++) acc[i][j][k] = 0.f;

    const int nStages = K / BK;
    issue(0);
    if (nStages > 1) issue(1);

    for (int c = 0; c < nStages; ++c) {
        if (c + 1 < nStages) { CP_WAIT1(); } else { CP_WAIT0(); }
        __syncthreads();

        const int s = c & 1;
        const __nv_bfloat16* sAh = smem + s * STAGE_ELEMS;
        const __nv_bfloat16* sAl = sAh + ARR_ELEMS;
        const __nv_bfloat16* sBh = sAl + ARR_ELEMS;
        const __nv_bfloat16* sBl = sBh + ARR_ELEMS;

        #pragma unroll
        for (int ks = 0; ks < BK; ks += 16) {
            uint32_t ah[4][4], al[4][4];
            #pragma unroll
            for (int ib = 0; ib < 4; ++ib) {
                const int rb = (wm + ib * 16 + g) * ST + ks + 2 * ti;
                ah[ib][0] = *reinterpret_cast<const uint32_t*>(sAh + rb);
                ah[ib][1] = *reinterpret_cast<const uint32_t*>(sAh + rb + 8 * ST);
                ah[ib][2] = *reinterpret_cast<const uint32_t*>(sAh + rb + 8);
                ah[ib][3] = *reinterpret_cast<const uint32_t*>(sAh + rb + 8 * ST + 8);
                al[ib][0] = *reinterpret_cast<const uint32_t*>(sAl + rb);
                al[ib][1] = *reinterpret_cast<const uint32_t*>(sAl + rb + 8 * ST);
                al[ib][2] = *reinterpret_cast<const uint32_t*>(sAl + rb + 8);
                al[ib][3] = *reinterpret_cast<const uint32_t*>(sAl + rb + 8 * ST + 8);
            }
            #pragma unroll
            for (int jb = 0; jb < 4; ++jb) {
                const int nb = (wn + jb * 8 + g) * ST + ks + 2 * ti;
                const uint32_t bh0 = *reinterpret_cast<const uint32_t*>(sBh + nb);
                const uint32_t bh1 = *reinterpret_cast<const uint32_t*>(sBh + nb + 8);
                const uint32_t bl0 = *reinterpret_cast<const uint32_t*>(sBl + nb);
                const uint32_t bl1 = *reinterpret_cast<const uint32_t*>(sBl + nb + 8);
                #pragma unroll
                for (int ib = 0; ib < 4; ++ib) {
                    mma_bf16(acc[ib][jb], ah[ib], bh0, bh1);   // hi*hi
                    mma_bf16(acc[ib][jb], ah[ib], bl0, bl1);   // hi*lo
                    mma_bf16(acc[ib][jb], al[ib], bh0, bh1);   // lo*hi
                }
            }
        }
        __syncthreads();
        if (c + 2 < nStages) issue(c + 2);
    }

    // Epilogue: c0,c1 at (g, 2ti/(+1)); c2,c3 at (g+8, ...)
    const int row0 = blockIdx.y * 128 + wm;
    const int col0 = blockIdx.x * 128 + wn;
    #pragma unroll
    for (int ib = 0; ib < 4; ++ib) {
        #pragma unroll
        for (int jb = 0; jb < 4; ++jb) {
            const int cc = col0 + jb * 8 + 2 * ti;
            #pragma unroll
            for (int half = 0; half < 2; half++) {
                const int r = row0 + ib * 16 + g + half * 8;
                float e0 = acc[ib][jb][half * 2 + 0];
                float e1 = acc[ib][jb][half * 2 + 1];
                const size_t off = (size_t)r * N + cc;
                if (EPI != EPI_NONE) {
                    e0 += bias[cc];
                    e1 += bias[cc + 1];
                }
                if (EPI == EPI_BIAS_RES) {
                    float2 rr = *reinterpret_cast<const float2*>(resid + off);
                    e0 += rr.x;
                    e1 += rr.y;
                }
                if (EPI == EPI_BIAS_GELU) {
                    e0 = 0.5f * e0 * (1.0f + erff(e0 * 0.70710678118654752f));
                    e1 = 0.5f * e1 * (1.0f + erff(e1 * 0.70710678118654752f));
                }
                if (OUTM == OUT_F32) {
                    *reinterpret_cast<float2*>(C + off) = make_float2(e0, e1);
                } else {
                    __nv_bfloat162 hh2, ll2;
                    bsplit(e0, hh2.x, ll2.x);
                    bsplit(e1, hh2.y, ll2.y);
                    *reinterpret_cast<__nv_bfloat162*>(Chi + off) = hh2;
                    *reinterpret_cast<__nv_bfloat162*>(Clo + off) = ll2;
                }
            }
        }
    }
}

// ---------------------------------------------------------------------------
// Flash attention, fp32; epilogue emits bf16 hi/lo for the out-proj GEMM.
// ---------------------------------------------------------------------------
struct AttSmem {
    float Qs [64][65];
    float KVs[64][65];
    float Ps [64][65];
    float red[64][16];
    float m_run[64];
    float l_run[64];
    float alpha[64];
    float m_cur[64];
};

__global__ void __launch_bounds__(256) attn_kernel(
    const float* __restrict__ qx, const float* __restrict__ kv,
    __nv_bfloat16* __restrict__ out_h, __nv_bfloat16* __restrict__ out_l)
{
    extern __shared__ unsigned char smem_raw[];
    AttSmem& sm = *reinterpret_cast<AttSmem*>(smem_raw);

    const int t  = threadIdx.x;
    const int tx = t & 15, ty = t >> 4;
    const int r0 = ty * 4, c0 = tx * 4;
    const int qb = blockIdx.x * 64;
    const int h  = blockIdx.y;
    const int b  = blockIdx.z;

    const float* qptr = qx + ((size_t)b * SEQ) * C_DIM  + (size_t)h * DH;
    const float* kptr = kv + ((size_t)b * SEQ) * KV_DIM + (size_t)h * DH;
    const float* vptr = kptr + C_DIM;

    #pragma unroll
    for (int i = 0; i < 4; i++) {
        int vi = t + i * 256;
        int r  = vi >> 4;
        int d  = (vi & 15) * 4;
        float4 q4 = *reinterpret_cast<const float4*>(qptr + (size_t)(qb + r) * C_DIM + d);
        sm.Qs[r][d + 0] = q4.x; sm.Qs[r][d + 1] = q4.y;
        sm.Qs[r][d + 2] = q4.z; sm.Qs[r][d + 3] = q4.w;
    }
    if (t < 64) { sm.m_run[t] = -INFINITY; sm.l_run[t] = 0.f; }

    float o[4][4] = {};
    __syncthreads();

    for (int kt = 0; kt < 16; ++kt) {
        const int kb = kt * 64;

        #pragma unroll
        for (int i = 0; i < 4; i++) {
            int vi = t + i * 256;
            int r  = vi >> 4;
            int d  = (vi & 15) * 4;
            float4 k4 = *reinterpret_cast<const float4*>(kptr + (size_t)(kb + r) * KV_DIM + d);
            sm.KVs[r][d + 0] = k4.x; sm.KVs[r][d + 1] = k4.y;
            sm.KVs[r][d + 2] = k4.z; sm.KVs[r][d + 3] = k4.w;
        }
        __syncthreads();

        float s[4][4] = {};
        #pragma unroll 4
        for (int d = 0; d < 64; ++d) {
            float qf[4], kf[4];
            #pragma unroll
            for (int i = 0; i < 4; i++) qf[i] = sm.Qs[r0 + i][d];
            #pragma unroll
            for (int j = 0; j < 4; j++) kf[j] = sm.KVs[c0 + j][d];
            #pragma unroll
            for (int i = 0; i < 4; i++)
                #pragma unroll
                for (int j = 0; j < 4; j++) s[i][j] += qf[i] * kf[j];
        }
        #pragma unroll
        for (int i = 0; i < 4; i++)
            #pragma unroll
            for (int j = 0; j < 4; j++) s[i][j] *= 0.125f;

        __syncthreads();

        #pragma unroll
        for (int i = 0; i < 4; i++) {
            float mx = fmaxf(fmaxf(s[i][0], s[i][1]), fmaxf(s[i][2], s[i][3]));
            sm.red[r0 + i][tx] = mx;
        }
        __syncthreads();

        if (t < 64) {
            float mx = sm.red[t][0];
            #pragma unroll
            for (int jj = 1; jj < 16; jj++) mx = fmaxf(mx, sm.red[t][jj]);
            float mo = sm.m_run[t];
            float mn = fmaxf(mo, mx);
            sm.m_cur[t]  = mn;
            sm.alpha[t]  = expf(mo - mn);
            sm.m_run[t]  = mn;
        }
        __syncthreads();

        #pragma unroll
        for (int i = 0; i < 4; i++) {
            float mn = sm.m_cur[r0 + i];
            float ps = 0.f;
            #pragma unroll
            for (int j = 0; j < 4; j++) {
                float p = expf(s[i][j] - mn);
                sm.Ps[r0 + i][c0 + j] = p;
                ps += p;
            }
            sm.red[r0 + i][tx] = ps;
        }
        #pragma unroll
        for (int i = 0; i < 4; i++) {
            int vi = t + i * 256;
            int r  = vi >> 4;
            int d  = (vi & 15) * 4;
            float4 v4 = *reinterpret_cast<const float4*>(vptr + (size_t)(kb + r) * KV_DIM + d);
            sm.KVs[r][d + 0] = v4.x; sm.KVs[r][d + 1] = v4.y;
            sm.KVs[r][d + 2] = v4.z; sm.KVs[r][d + 3] = v4.w;
        }
        __syncthreads();

        if (t < 64) {
            float su = 0.f;
            #pragma unroll
            for (int jj = 0; jj < 16; jj++) su += sm.red[t][jj];
            sm.l_run[t] = sm.alpha[t] * sm.l_run[t] + su;
        }

        #pragma unroll
        for (int i = 0; i < 4; i++) {
            float a = sm.alpha[r0 + i];
            #pragma unroll
            for (int j = 0; j < 4; j++) o[i][j] *= a;
        }
        #pragma unroll 4
        for (int kk = 0; kk < 64; ++kk) {
            float pf[4], vf[4];
            #pragma unroll
            for (int i = 0; i < 4; i++) pf[i] = sm.Ps[r0 + i][kk];
            #pragma unroll
            for (int j = 0; j < 4; j++) vf[j] = sm.KVs[kk][c0 + j];
            #pragma unroll
            for (int i = 0; i < 4; i++)
                #pragma unroll
                for (int j = 0; j < 4; j++) o[i][j] += pf[i] * vf[j];
        }
        __syncthreads();
    }

    #pragma unroll
    for (int i = 0; i < 4; i++) {
        float inv = 1.0f / sm.l_run[r0 + i];
        const size_t off = ((size_t)b * SEQ + qb + r0 + i) * C_DIM + h * DH + c0;
        __nv_bfloat162 h01, h23, l01, l23;
        bsplit(o[i][0] * inv, h01.x, l01.x);
        bsplit(o[i][1] * inv, h01.y, l01.y);
        bsplit(o[i][2] * inv, h23.x, l23.x);
        bsplit(o[i][3] * inv, h23.y, l23.y);
        *reinterpret_cast<__nv_bfloat162*>(out_h + off)     = h01;
        *reinterpret_cast<__nv_bfloat162*>(out_h + off + 2) = h23;
        *reinterpret_cast<__nv_bfloat162*>(out_l + off)     = l01;
        *reinterpret_cast<__nv_bfloat162*>(out_l + off + 2) = l23;
    }
}

// ---------------------------------------------------------------------------
// Launch
// ---------------------------------------------------------------------------
extern "C" void kernel_launch(void* const* d_in, const int* in_sizes, int n_in,
                              void* d_out, int out_size)
{
    const float* x       = (const float*)d_in[0];
    const float* q_extra = (const float*)d_in[1];
    const float* ln1_g   = (const float*)d_in[2];
    const float* ln1_b   = (const float*)d_in[3];
    const float* w_kv    = (const float*)d_in[4];
    const float* w_out   = (const float*)d_in[5];
    const float* b_out   = (const float*)d_in[6];
    const float* ln2_g   = (const float*)d_in[7];
    const float* ln2_b   = (const float*)d_in[8];
    const float* w1      = (const float*)d_in[9];
    const float* b1      = (const float*)d_in[10];
    const float* w2      = (const float*)d_in[11];
    const float* b2      = (const float*)d_in[12];
    float* out = (float*)d_out;

    __nv_bfloat16 *xn_h, *xn_l, *att_h, *att_l, *h_h, *h_l, *hh_h, *hh_l;
    __nv_bfloat16 *wkv_h, *wkv_l, *wout_h, *wout_l, *w1_h, *w1_l, *w2_h, *w2_l;
    float *kvp, *x2;
    cudaGetSymbolAddress((void**)&xn_h,  g_xn_h);  cudaGetSymbolAddress((void**)&xn_l,  g_xn_l);
    cudaGetSymbolAddress((void**)&att_h, g_att_h); cudaGetSymbolAddress((void**)&att_l, g_att_l);
    cudaGetSymbolAddress((void**)&h_h,   g_h_h);   cudaGetSymbolAddress((void**)&h_l,   g_h_l);
    cudaGetSymbolAddress((void**)&hh_h,  g_hh_h);  cudaGetSymbolAddress((void**)&hh_l,  g_hh_l);
    cudaGetSymbolAddress((void**)&wkv_h, g_wkv_h); cudaGetSymbolAddress((void**)&wkv_l, g_wkv_l);
    cudaGetSymbolAddress((void**)&wout_h,g_wout_h);cudaGetSymbolAddress((void**)&wout_l,g_wout_l);
    cudaGetSymbolAddress((void**)&w1_h,  g_w1_h);  cudaGetSymbolAddress((void**)&w1_l,  g_w1_l);
    cudaGetSymbolAddress((void**)&w2_h,  g_w2_h);  cudaGetSymbolAddress((void**)&w2_l,  g_w2_l);
    cudaGetSymbolAddress((void**)&kvp,   g_kv);
    cudaGetSymbolAddress((void**)&x2,    g_x2);

    cudaFuncSetAttribute(attn_kernel, cudaFuncAttributeMaxDynamicSharedMemorySize,
                         (int)sizeof(AttSmem));
    cudaFuncSetAttribute(tgemm_bf3<EPI_NONE, OUT_F32>,
                         cudaFuncAttributeMaxDynamicSharedMemorySize, TG_SMEM);
    cudaFuncSetAttribute(tgemm_bf3<EPI_BIAS_RES, OUT_F32>,
                         cudaFuncAttributeMaxDynamicSharedMemorySize, TG_SMEM);
    cudaFuncSetAttribute(tgemm_bf3<EPI_BIAS_GELU, OUT_BF16>,
                         cudaFuncAttributeMaxDynamicSharedMemorySize, TG_SMEM);

    // 0) Weight transpose + bf16 split: [K,N] -> [N,K] hi/lo
    wsplit_t<<<dim3(KV_DIM / 32, C_DIM / 32), dim3(32, 8)>>>(w_kv,  wkv_h,  wkv_l,  C_DIM, KV_DIM);
    wsplit_t<<<dim3(C_DIM / 32,  C_DIM / 32), dim3(32, 8)>>>(w_out, wout_h, wout_l, C_DIM, C_DIM);
    wsplit_t<<<dim3(HID / 32,    C_DIM / 32), dim3(32, 8)>>>(w1,    w1_h,   w1_l,   C_DIM, HID);
    wsplit_t<<<dim3(C_DIM / 32,  HID / 32),   dim3(32, 8)>>>(w2,    w2_h,   w2_l,   HID,   C_DIM);

    // 1) xn = LN1(x)  (bf16 hi/lo)
    ln_kernel<<<TOKENS, 256>>>(x, ln1_g, ln1_b, xn_h, xn_l);

    // 2) kv = xn @ w_kv            [8192 x 1536, K=768]
    tgemm_bf3<EPI_NONE, OUT_F32><<<dim3(KV_DIM / 128, TOKENS / 128), 256, TG_SMEM>>>(
        TOKENS, KV_DIM, C_DIM, xn_h, xn_l, wkv_h, wkv_l,
        nullptr, nullptr, kvp, nullptr, nullptr);

    // 3) att = softmax(q k^T / 8) v   (bf16 hi/lo)
    attn_kernel<<<dim3(SEQ / 64, HEADS, BATCH), 256, sizeof(AttSmem)>>>(
        q_extra, kvp, att_h, att_l);

    // 4) x2 = x + att @ w_out + b_out   [8192 x 768, K=768]
    tgemm_bf3<EPI_BIAS_RES, OUT_F32><<<dim3(C_DIM / 128, TOKENS / 128), 256, TG_SMEM>>>(
        TOKENS, C_DIM, C_DIM, att_h, att_l, wout_h, wout_l,
        b_out, x, x2, nullptr, nullptr);

    // 5) h = LN2(x2)   (bf16 hi/lo)
    ln_kernel<<<TOKENS, 256>>>(x2, ln2_g, ln2_b, h_h, h_l);

    // 6) hh = gelu(h @ w1 + b1)   [8192 x 3072, K=768] (bf16 hi/lo)
    tgemm_bf3<EPI_BIAS_GELU, OUT_BF16><<<dim3(HID / 128, TOKENS / 128), 256, TG_SMEM>>>(
        TOKENS, HID, C_DIM, h_h, h_l, w1_h, w1_l,
        b1, nullptr, nullptr, hh_h, hh_l);

    // 7) out = x2 + hh @ w2 + b2   [8192 x 768, K=3072]
    tgemm_bf3<EPI_BIAS_RES, OUT_F32><<<dim3(C_DIM / 128, TOKENS / 128), 256, TG_SMEM>>>(
        TOKENS, C_DIM, HID, hh_h, hh_l, w2_h, w2_l,
        b2, x2, out, nullptr, nullptr);
}

// round 11
// speedup vs baseline: 1.8929x; 1.0003x over previous
#include <cuda_runtime.h>
#include <cuda_bf16.h>
#include <math.h>
#include <stdint.h>

// Problem constants
#define TOKENS 8192      // B*N = 8*1024
#define BATCH  8
#define SEQ    1024
#define C_DIM  768
#define KV_DIM 1536
#define HID    3072
#define HEADS  12
#define DH     64

// ---------------------------------------------------------------------------
// Scratch (device globals; no runtime allocation)
// ---------------------------------------------------------------------------
__device__ __nv_bfloat16 g_xn_h [TOKENS * C_DIM];
__device__ __nv_bfloat16 g_xn_l [TOKENS * C_DIM];
__device__ float         g_kv   [TOKENS * KV_DIM];
__device__ __nv_bfloat16 g_att_h[TOKENS * C_DIM];
__device__ __nv_bfloat16 g_att_l[TOKENS * C_DIM];
__device__ float         g_x2   [TOKENS * C_DIM];
__device__ __nv_bfloat16 g_h_h  [TOKENS * C_DIM];
__device__ __nv_bfloat16 g_h_l  [TOKENS * C_DIM];
__device__ __nv_bfloat16 g_hh_h [TOKENS * HID];
__device__ __nv_bfloat16 g_hh_l [TOKENS * HID];

// Transposed + bf16-split weights: [N, K] row-major (i.e. W^T)
__device__ __nv_bfloat16 g_wkv_h [KV_DIM * C_DIM];
__device__ __nv_bfloat16 g_wkv_l [KV_DIM * C_DIM];
__device__ __nv_bfloat16 g_wout_h[C_DIM * C_DIM];
__device__ __nv_bfloat16 g_wout_l[C_DIM * C_DIM];
__device__ __nv_bfloat16 g_w1_h  [HID * C_DIM];
__device__ __nv_bfloat16 g_w1_l  [HID * C_DIM];
__device__ __nv_bfloat16 g_w2_h  [C_DIM * HID];
__device__ __nv_bfloat16 g_w2_l  [C_DIM * HID];

// ---------------------------------------------------------------------------
// Helpers
// ---------------------------------------------------------------------------
__device__ __forceinline__ void bsplit(float v, __nv_bfloat16& h, __nv_bfloat16& l) {
    h = __float2bfloat16(v);
    l = __float2bfloat16(v - __bfloat162float(h));
}

// bf16 m16n8k16 MMA (row.col), fp32 accumulate — supported on plain sm_103
__device__ __forceinline__ void mma_bf16(float* c, const uint32_t* a,
                                         uint32_t b0, uint32_t b1) {
    asm volatile(
        "mma.sync.aligned.m16n8k16.row.col.f32.bf16.bf16.f32 "
        "{%0,%1,%2,%3}, {%4,%5,%6,%7}, {%8,%9}, {%0,%1,%2,%3};"
        : "+f"(c[0]), "+f"(c[1]), "+f"(c[2]), "+f"(c[3])
        : "r"(a[0]), "r"(a[1]), "r"(a[2]), "r"(a[3]), "r"(b0), "r"(b1));
}

#define CP_ASYNC16(smem_u32, gptr) \
    asm volatile("cp.async.cg.shared.global [%0], [%1], 16;" \
        :: "r"(smem_u32), "l"(gptr) : "memory")
#define CP_COMMIT() asm volatile("cp.async.commit_group;" ::: "memory")
#define CP_WAIT1()  asm volatile("cp.async.wait_group 1;" ::: "memory")
#define CP_WAIT0()  asm volatile("cp.async.wait_group 0;" ::: "memory")

// ---------------------------------------------------------------------------
// Weight transpose + bf16 split: w[K,N] fp32 -> th/tl[N,K] bf16
// ---------------------------------------------------------------------------
__global__ void __launch_bounds__(256) wsplit_t(
    const float* __restrict__ w, __nv_bfloat16* __restrict__ th,
    __nv_bfloat16* __restrict__ tl, int K, int N)
{
    __shared__ float tile[32][33];
    const int n0 = blockIdx.x * 32, k0 = blockIdx.y * 32;
    const int tx = threadIdx.x, ty = threadIdx.y;
    #pragma unroll
    for (int i = ty; i < 32; i += 8)
        tile[i][tx] = w[(size_t)(k0 + i) * N + n0 + tx];
    __syncthreads();
    #pragma unroll
    for (int i = ty; i < 32; i += 8) {
        float v = tile[tx][i];                 // = w[k0+tx][n0+i]
        __nv_bfloat16 h, l; bsplit(v, h, l);
        size_t o = (size_t)(n0 + i) * K + k0 + tx;
        th[o] = h; tl[o] = l;
    }
}

// ---------------------------------------------------------------------------
// LayerNorm -> bf16 hi/lo outputs
// ---------------------------------------------------------------------------
__global__ void __launch_bounds__(256) ln_kernel(
    const float* __restrict__ x, const float* __restrict__ g,
    const float* __restrict__ b,
    __nv_bfloat16* __restrict__ hi, __nv_bfloat16* __restrict__ lo)
{
    __shared__ float sh[9];
    const int row = blockIdx.x;
    const int t = threadIdx.x;
    const float* xr = x + (size_t)row * C_DIM;

    float v0 = xr[t], v1 = xr[t + 256], v2 = xr[t + 512];

    float s = v0 + v1 + v2;
    #pragma unroll
    for (int o = 16; o; o >>= 1) s += __shfl_xor_sync(0xffffffffu, s, o);
    if ((t & 31) == 0) sh[t >> 5] = s;
    __syncthreads();
    if (t == 0) {
        float a = 0.f;
        #pragma unroll
        for (int i = 0; i < 8; i++) a += sh[i];
        sh[8] = a * (1.0f / C_DIM);
    }
    __syncthreads();
    const float mu = sh[8];

    float d0 = v0 - mu, d1 = v1 - mu, d2 = v2 - mu;
    float q = d0 * d0 + d1 * d1 + d2 * d2;
    __syncthreads();
    #pragma unroll
    for (int o = 16; o; o >>= 1) q += __shfl_xor_sync(0xffffffffu, q, o);
    if ((t & 31) == 0) sh[t >> 5] = q;
    __syncthreads();
    if (t == 0) {
        float a = 0.f;
        #pragma unroll
        for (int i = 0; i < 8; i++) a += sh[i];
        sh[8] = rsqrtf(a * (1.0f / C_DIM) + 1e-5f);
    }
    __syncthreads();
    const float rs = sh[8];

    const size_t rb = (size_t)row * C_DIM;
    float vals[3] = { d0 * rs * g[t] + b[t],
                      d1 * rs * g[t + 256] + b[t + 256],
                      d2 * rs * g[t + 512] + b[t + 512] };
    #pragma unroll
    for (int i = 0; i < 3; i++) {
        __nv_bfloat16 h, l; bsplit(vals[i], h, l);
        hi[rb + t + i * 256] = h;
        lo[rb + t + i * 256] = l;
    }
}

// ---------------------------------------------------------------------------
// bf16x3 tensor-core GEMM: C[M,N] = A @ Bt^T (+bias)(+resid | GELU)
// A: bf16 hi/lo [M,K] row-major; Bt: bf16 hi/lo [N,K] row-major.
// mma.m16n8k16 bf16, fp32 accum. Block tile 128x128, BK=32, 256 thr, 8 warps
// (2x4, warp tile 64x32). cp.async double-buffered smem, stride-40 layout
// (bank = (20g+ti)%32 — conflict-free fragment reads).
// ---------------------------------------------------------------------------
enum { EPI_NONE = 0, EPI_BIAS_RES = 1, EPI_BIAS_GELU = 2 };
enum { OUT_F32 = 0, OUT_BF16 = 1 };

#define BK 32
#define ST 40                       // smem row stride in bf16 elems
#define ARR_ELEMS (128 * ST)        // 5120 bf16 = 10240 B per array
#define STAGE_ELEMS (4 * ARR_ELEMS) // Ah, Al, Bh, Bl
#define TG_SMEM (2 * STAGE_ELEMS * 2)  // bytes = 81920

template <int EPI, int OUTM>
__global__ void __launch_bounds__(256) tgemm_bf3(
    int M, int N, int K,
    const __nv_bfloat16* __restrict__ Ahi, const __nv_bfloat16* __restrict__ Alo,
    const __nv_bfloat16* __restrict__ Bth, const __nv_bfloat16* __restrict__ Btl,
    const float* __restrict__ bias, const float* __restrict__ resid,
    float* __restrict__ C,
    __nv_bfloat16* __restrict__ Chi, __nv_bfloat16* __restrict__ Clo)
{
    extern __shared__ __nv_bfloat16 smem[];
    const uint32_t smb = (uint32_t)__cvta_generic_to_shared(smem);

    const int t    = threadIdx.x;
    const int lane = t & 31;
    const int warp = t >> 5;
    const int wm   = (warp >> 2) * 64;   // 0 or 64
    const int wn   = (warp & 3) * 32;    // 0,32,64,96
    const int g    = lane >> 2;          // 0..7
    const int ti   = lane & 3;           // 0..3

    const __nv_bfloat16* Ab_h = Ahi + (size_t)blockIdx.y * 128 * K;
    const __nv_bfloat16* Ab_l = Alo + (size_t)blockIdx.y * 128 * K;
    const __nv_bfloat16* Bb_h = Bth + (size_t)blockIdx.x * 128 * K;
    const __nv_bfloat16* Bb_l = Btl + (size_t)blockIdx.x * 128 * K;
    const __nv_bfloat16* srcs[4] = { Ab_h, Ab_l, Bb_h, Bb_l };

    // loader: per array 128 rows x 32 cols bf16 = 512 uint4; 2 per thread
    const int r0l = (t) >> 2,        q0l = (t) & 3;
    const int r1l = (t + 256) >> 2,  q1l = (t + 256) & 3;

    auto issue = [&](int c) {
        const int s = c & 1;
        const uint32_t sb = smb + s * (STAGE_ELEMS * 2);
        #pragma unroll
        for (int arr = 0; arr < 4; ++arr) {
            const __nv_bfloat16* src = srcs[arr] + c * BK;
            const uint32_t db = sb + arr * (ARR_ELEMS * 2);
            CP_ASYNC16(db + (uint32_t)(r0l * (ST * 2) + q0l * 16),
                       src + (size_t)r0l * K + q0l * 8);
            CP_ASYNC16(db + (uint32_t)(r1l * (ST * 2) + q1l * 16),
                       src + (size_t)r1l * K + q1l * 8);
        }
        CP_COMMIT();
    };

    float acc[4][4][4];
    #pragma unroll
    for (int i = 0; i < 4; i++)
        #pragma unroll
        for (int j = 0; j < 4; j++)
            #pragma unroll
            for (int k = 0; k < 4; k++) acc[i][j][k] = 0.f;

    const int nStages = K / BK;
    issue(0);
    if (nStages > 1) issue(1);

    for (int c = 0; c < nStages; ++c) {
        if (c + 1 < nStages) { CP_WAIT1(); } else { CP_WAIT0(); }
        __syncthreads();

        const int s = c & 1;
        const __nv_bfloat16* sAh = smem + s * STAGE_ELEMS;
        const __nv_bfloat16* sAl = sAh + ARR_ELEMS;
        const __nv_bfloat16* sBh = sAl + ARR_ELEMS;
        const __nv_bfloat16* sBl = sBh + ARR_ELEMS;

        #pragma unroll
        for (int ks = 0; ks < BK; ks += 16) {
            uint32_t ah[4][4], al[4][4];
            #pragma unroll
            for (int ib = 0; ib < 4; ++ib) {
                const int rb = (wm + ib * 16 + g) * ST + ks + 2 * ti;
                ah[ib][0] = *reinterpret_cast<const uint32_t*>(sAh + rb);
                ah[ib][1] = *reinterpret_cast<const uint32_t*>(sAh + rb + 8 * ST);
                ah[ib][2] = *reinterpret_cast<const uint32_t*>(sAh + rb + 8);
                ah[ib][3] = *reinterpret_cast<const uint32_t*>(sAh + rb + 8 * ST + 8);
                al[ib][0] = *reinterpret_cast<const uint32_t*>(sAl + rb);
                al[ib][1] = *reinterpret_cast<const uint32_t*>(sAl + rb + 8 * ST);
                al[ib][2] = *reinterpret_cast<const uint32_t*>(sAl + rb + 8);
                al[ib][3] = *reinterpret_cast<const uint32_t*>(sAl + rb + 8 * ST + 8);
            }
            #pragma unroll
            for (int jb = 0; jb < 4; ++jb) {
                const int nb = (wn + jb * 8 + g) * ST + ks + 2 * ti;
                const uint32_t bh0 = *reinterpret_cast<const uint32_t*>(sBh + nb);
                const uint32_t bh1 = *reinterpret_cast<const uint32_t*>(sBh + nb + 8);
                const uint32_t bl0 = *reinterpret_cast<const uint32_t*>(sBl + nb);
                const uint32_t bl1 = *reinterpret_cast<const uint32_t*>(sBl + nb + 8);
                #pragma unroll
                for (int ib = 0; ib < 4; ++ib) {
                    mma_bf16(acc[ib][jb], ah[ib], bh0, bh1);   // hi*hi
                    mma_bf16(acc[ib][jb], ah[ib], bl0, bl1);   // hi*lo
                    mma_bf16(acc[ib][jb], al[ib], bh0, bh1);   // lo*hi
                }
            }
        }
        __syncthreads();
        if (c + 2 < nStages) issue(c + 2);
    }

    // Epilogue: c0,c1 at (g, 2ti/(+1)); c2,c3 at (g+8, ...)
    const int row0 = blockIdx.y * 128 + wm;
    const int col0 = blockIdx.x * 128 + wn;
    #pragma unroll
    for (int ib = 0; ib < 4; ++ib) {
        #pragma unroll
        for (int jb = 0; jb < 4; ++jb) {
            const int cc = col0 + jb * 8 + 2 * ti;
            #pragma unroll
            for (int half = 0; half < 2; half++) {
                const int r = row0 + ib * 16 + g + half * 8;
                float e0 = acc[ib][jb][half * 2 + 0];
                float e1 = acc[ib][jb][half * 2 + 1];
                const size_t off = (size_t)r * N + cc;
                if (EPI != EPI_NONE) {
                    e0 += bias[cc];
                    e1 += bias[cc + 1];
                }
                if (EPI == EPI_BIAS_RES) {
                    float2 rr = *reinterpret_cast<const float2*>(resid + off);
                    e0 += rr.x;
                    e1 += rr.y;
                }
                if (EPI == EPI_BIAS_GELU) {
                    e0 = 0.5f * e0 * (1.0f + erff(e0 * 0.70710678118654752f));
                    e1 = 0.5f * e1 * (1.0f + erff(e1 * 0.70710678118654752f));
                }
                if (OUTM == OUT_F32) {
                    *reinterpret_cast<float2*>(C + off) = make_float2(e0, e1);
                } else {
                    __nv_bfloat162 hh2, ll2;
                    bsplit(e0, hh2.x, ll2.x);
                    bsplit(e1, hh2.y, ll2.y);
                    *reinterpret_cast<__nv_bfloat162*>(Chi + off) = hh2;
                    *reinterpret_cast<__nv_bfloat162*>(Clo + off) = ll2;
                }
            }
        }
    }
}

// ---------------------------------------------------------------------------
// Flash attention, fp32; epilogue emits bf16 hi/lo for the out-proj GEMM.
// ---------------------------------------------------------------------------
struct AttSmem {
    float Qs [64][65];
    float KVs[64][65];
    float Ps [64][65];
    float red[64][16];
    float m_run[64];
    float l_run[64];
    float alpha[64];
    float m_cur[64];
};

__global__ void __launch_bounds__(256) attn_kernel(
    const float* __restrict__ qx, const float* __restrict__ kv,
    __nv_bfloat16* __restrict__ out_h, __nv_bfloat16* __restrict__ out_l)
{
    extern __shared__ unsigned char smem_raw[];
    AttSmem& sm = *reinterpret_cast<AttSmem*>(smem_raw);

    const int t  = threadIdx.x;
    const int tx = t & 15, ty = t >> 4;
    const int r0 = ty * 4, c0 = tx * 4;
    const int qb = blockIdx.x * 64;
    const int h  = blockIdx.y;
    const int b  = blockIdx.z;

    const float* qptr = qx + ((size_t)b * SEQ) * C_DIM  + (size_t)h * DH;
    const float* kptr = kv + ((size_t)b * SEQ) * KV_DIM + (size_t)h * DH;
    const float* vptr = kptr + C_DIM;

    #pragma unroll
    for (int i = 0; i < 4; i++) {
        int vi = t + i * 256;
        int r  = vi >> 4;
        int d  = (vi & 15) * 4;
        float4 q4 = *reinterpret_cast<const float4*>(qptr + (size_t)(qb + r) * C_DIM + d);
        sm.Qs[r][d + 0] = q4.x; sm.Qs[r][d + 1] = q4.y;
        sm.Qs[r][d + 2] = q4.z; sm.Qs[r][d + 3] = q4.w;
    }
    if (t < 64) { sm.m_run[t] = -INFINITY; sm.l_run[t] = 0.f; }

    float o[4][4] = {};
    __syncthreads();

    for (int kt = 0; kt < 16; ++kt) {
        const int kb = kt * 64;

        #pragma unroll
        for (int i = 0; i < 4; i++) {
            int vi = t + i * 256;
            int r  = vi >> 4;
            int d  = (vi & 15) * 4;
            float4 k4 = *reinterpret_cast<const float4*>(kptr + (size_t)(kb + r) * KV_DIM + d);
            sm.KVs[r][d + 0] = k4.x; sm.KVs[r][d + 1] = k4.y;
            sm.KVs[r][d + 2] = k4.z; sm.KVs[r][d + 3] = k4.w;
        }
        __syncthreads();

        float s[4][4] = {};
        #pragma unroll 4
        for (int d = 0; d < 64; ++d) {
            float qf[4], kf[4];
            #pragma unroll
            for (int i = 0; i < 4; i++) qf[i] = sm.Qs[r0 + i][d];
            #pragma unroll
            for (int j = 0; j < 4; j++) kf[j] = sm.KVs[c0 + j][d];
            #pragma unroll
            for (int i = 0; i < 4; i++)
                #pragma unroll
                for (int j = 0; j < 4; j++) s[i][j] += qf[i] * kf[j];
        }
        #pragma unroll
        for (int i = 0; i < 4; i++)
            #pragma unroll
            for (int j = 0; j < 4; j++) s[i][j] *= 0.125f;

        __syncthreads();

        #pragma unroll
        for (int i = 0; i < 4; i++) {
            float mx = fmaxf(fmaxf(s[i][0], s[i][1]), fmaxf(s[i][2], s[i][3]));
            sm.red[r0 + i][tx] = mx;
        }
        __syncthreads();

        if (t < 64) {
            float mx = sm.red[t][0];
            #pragma unroll
            for (int jj = 1; jj < 16; jj++) mx = fmaxf(mx, sm.red[t][jj]);
            float mo = sm.m_run[t];
            float mn = fmaxf(mo, mx);
            sm.m_cur[t]  = mn;
            sm.alpha[t]  = expf(mo - mn);
            sm.m_run[t]  = mn;
        }
        __syncthreads();

        #pragma unroll
        for (int i = 0; i < 4; i++) {
            float mn = sm.m_cur[r0 + i];
            float ps = 0.f;
            #pragma unroll
            for (int j = 0; j < 4; j++) {
                float p = expf(s[i][j] - mn);
                sm.Ps[r0 + i][c0 + j] = p;
                ps += p;
            }
            sm.red[r0 + i][tx] = ps;
        }
        #pragma unroll
        for (int i = 0; i < 4; i++) {
            int vi = t + i * 256;
            int r  = vi >> 4;
            int d  = (vi & 15) * 4;
            float4 v4 = *reinterpret_cast<const float4*>(vptr + (size_t)(kb + r) * KV_DIM + d);
            sm.KVs[r][d + 0] = v4.x; sm.KVs[r][d + 1] = v4.y;
            sm.KVs[r][d + 2] = v4.z; sm.KVs[r][d + 3] = v4.w;
        }
        __syncthreads();

        if (t < 64) {
            float su = 0.f;
            #pragma unroll
            for (int jj = 0; jj < 16; jj++) su += sm.red[t][jj];
            sm.l_run[t] = sm.alpha[t] * sm.l_run[t] + su;
        }

        #pragma unroll
        for (int i = 0; i < 4; i++) {
            float a = sm.alpha[r0 + i];
            #pragma unroll
            for (int j = 0; j < 4; j++) o[i][j] *= a;
        }
        #pragma unroll 4
        for (int kk = 0; kk < 64; ++kk) {
            float pf[4], vf[4];
            #pragma unroll
            for (int i = 0; i < 4; i++) pf[i] = sm.Ps[r0 + i][kk];
            #pragma unroll
            for (int j = 0; j < 4; j++) vf[j] = sm.KVs[kk][c0 + j];
            #pragma unroll
            for (int i = 0; i < 4; i++)
                #pragma unroll
                for (int j = 0; j < 4; j++) o[i][j] += pf[i] * vf[j];
        }
        __syncthreads();
    }

    #pragma unroll
    for (int i = 0; i < 4; i++) {
        float inv = 1.0f / sm.l_run[r0 + i];
        const size_t off = ((size_t)b * SEQ + qb + r0 + i) * C_DIM + h * DH + c0;
        __nv_bfloat162 h01, h23, l01, l23;
        bsplit(o[i][0] * inv, h01.x, l01.x);
        bsplit(o[i][1] * inv, h01.y, l01.y);
        bsplit(o[i][2] * inv, h23.x, l23.x);
        bsplit(o[i][3] * inv, h23.y, l23.y);
        *reinterpret_cast<__nv_bfloat162*>(out_h + off)     = h01;
        *reinterpret_cast<__nv_bfloat162*>(out_h + off + 2) = h23;
        *reinterpret_cast<__nv_bfloat162*>(out_l + off)     = l01;
        *reinterpret_cast<__nv_bfloat162*>(out_l + off + 2) = l23;
    }
}

// ---------------------------------------------------------------------------
// Launch
// ---------------------------------------------------------------------------
extern "C" void kernel_launch(void* const* d_in, const int* in_sizes, int n_in,
                              void* d_out, int out_size)
{
    const float* x       = (const float*)d_in[0];
    const float* q_extra = (const float*)d_in[1];
    const float* ln1_g   = (const float*)d_in[2];
    const float* ln1_b   = (const float*)d_in[3];
    const float* w_kv    = (const float*)d_in[4];
    const float* w_out   = (const float*)d_in[5];
    const float* b_out   = (const float*)d_in[6];
    const float* ln2_g   = (const float*)d_in[7];
    const float* ln2_b   = (const float*)d_in[8];
    const float* w1      = (const float*)d_in[9];
    const float* b1      = (const float*)d_in[10];
    const float* w2      = (const float*)d_in[11];
    const float* b2      = (const float*)d_in[12];
    float* out = (float*)d_out;

    __nv_bfloat16 *xn_h, *xn_l, *att_h, *att_l, *h_h, *h_l, *hh_h, *hh_l;
    __nv_bfloat16 *wkv_h, *wkv_l, *wout_h, *wout_l, *w1_h, *w1_l, *w2_h, *w2_l;
    float *kvp, *x2;
    cudaGetSymbolAddress((void**)&xn_h,  g_xn_h);  cudaGetSymbolAddress((void**)&xn_l,  g_xn_l);
    cudaGetSymbolAddress((void**)&att_h, g_att_h); cudaGetSymbolAddress((void**)&att_l, g_att_l);
    cudaGetSymbolAddress((void**)&h_h,   g_h_h);   cudaGetSymbolAddress((void**)&h_l,   g_h_l);
    cudaGetSymbolAddress((void**)&hh_h,  g_hh_h);  cudaGetSymbolAddress((void**)&hh_l,  g_hh_l);
    cudaGetSymbolAddress((void**)&wkv_h, g_wkv_h); cudaGetSymbolAddress((void**)&wkv_l, g_wkv_l);
    cudaGetSymbolAddress((void**)&wout_h,g_wout_h);cudaGetSymbolAddress((void**)&wout_l,g_wout_l);
    cudaGetSymbolAddress((void**)&w1_h,  g_w1_h);  cudaGetSymbolAddress((void**)&w1_l,  g_w1_l);
    cudaGetSymbolAddress((void**)&w2_h,  g_w2_h);  cudaGetSymbolAddress((void**)&w2_l,  g_w2_l);
    cudaGetSymbolAddress((void**)&kvp,   g_kv);
    cudaGetSymbolAddress((void**)&x2,    g_x2);

    cudaFuncSetAttribute(attn_kernel, cudaFuncAttributeMaxDynamicSharedMemorySize,
                         (int)sizeof(AttSmem));
    cudaFuncSetAttribute(tgemm_bf3<EPI_NONE, OUT_F32>,
                         cudaFuncAttributeMaxDynamicSharedMemorySize, TG_SMEM);
    cudaFuncSetAttribute(tgemm_bf3<EPI_BIAS_RES, OUT_F32>,
                         cudaFuncAttributeMaxDynamicSharedMemorySize, TG_SMEM);
    cudaFuncSetAttribute(tgemm_bf3<EPI_BIAS_GELU, OUT_BF16>,
                         cudaFuncAttributeMaxDynamicSharedMemorySize, TG_SMEM);

    // 0) Weight transpose + bf16 split: [K,N] -> [N,K] hi/lo
    wsplit_t<<<dim3(KV_DIM / 32, C_DIM / 32), dim3(32, 8)>>>(w_kv,  wkv_h,  wkv_l,  C_DIM, KV_DIM);
    wsplit_t<<<dim3(C_DIM / 32,  C_DIM / 32), dim3(32, 8)>>>(w_out, wout_h, wout_l, C_DIM, C_DIM);
    wsplit_t<<<dim3(HID / 32,    C_DIM / 32), dim3(32, 8)>>>(w1,    w1_h,   w1_l,   C_DIM, HID);
    wsplit_t<<<dim3(C_DIM / 32,  HID / 32),   dim3(32, 8)>>>(w2,    w2_h,   w2_l,   HID,   C_DIM);

    // 1) xn = LN1(x)  (bf16 hi/lo)
    ln_kernel<<<TOKENS, 256>>>(x, ln1_g, ln1_b, xn_h, xn_l);

    // 2) kv = xn @ w_kv            [8192 x 1536, K=768]
    tgemm_bf3<EPI_NONE, OUT_F32><<<dim3(KV_DIM / 128, TOKENS / 128), 256, TG_SMEM>>>(
        TOKENS, KV_DIM, C_DIM, xn_h, xn_l, wkv_h, wkv_l,
        nullptr, nullptr, kvp, nullptr, nullptr);

    // 3) att = softmax(q k^T / 8) v   (bf16 hi/lo)
    attn_kernel<<<dim3(SEQ / 64, HEADS, BATCH), 256, sizeof(AttSmem)>>>(
        q_extra, kvp, att_h, att_l);

    // 4) x2 = x + att @ w_out + b_out   [8192 x 768, K=768]
    tgemm_bf3<EPI_BIAS_RES, OUT_F32><<<dim3(C_DIM / 128, TOKENS / 128), 256, TG_SMEM>>>(
        TOKENS, C_DIM, C_DIM, att_h, att_l, wout_h, wout_l,
        b_out, x, x2, nullptr, nullptr);

    // 5) h = LN2(x2)   (bf16 hi/lo)
    ln_kernel<<<TOKENS, 256>>>(x2, ln2_g, ln2_b, h_h, h_l);

    // 6) hh = gelu(h @ w1 + b1)   [8192 x 3072, K=768] (bf16 hi/lo)
    tgemm_bf3<EPI_BIAS_GELU, OUT_BF16><<<dim3(HID / 128, TOKENS / 128), 256, TG_SMEM>>>(
        TOKENS, HID, C_DIM, h_h, h_l, w1_h, w1_l,
        b1, nullptr, nullptr, hh_h, hh_l);

    // 7) out = x2 + hh @ w2 + b2   [8192 x 768, K=3072]
    tgemm_bf3<EPI_BIAS_RES, OUT_F32><<<dim3(C_DIM / 128, TOKENS / 128), 256, TG_SMEM>>>(
        TOKENS, C_DIM, HID, hh_h, hh_l, w2_h, w2_l,
        b2, x2, out, nullptr, nullptr);
}

// round 12
// speedup vs baseline: 1.8933x; 1.0002x over previous
#include <cuda_runtime.h>
#include <cuda_bf16.h>
#include <math.h>
#include <stdint.h>

// Problem constants
#define TOKENS 8192      // B*N = 8*1024
#define BATCH  8
#define SEQ    1024
#define C_DIM  768
#define KV_DIM 1536
#define HID    3072
#define HEADS  12
#define DH     64

// ---------------------------------------------------------------------------
// Scratch (device globals; no runtime allocation)
// ---------------------------------------------------------------------------
__device__ __nv_bfloat16 g_xn_h [TOKENS * C_DIM];
__device__ __nv_bfloat16 g_xn_l [TOKENS * C_DIM];
__device__ float         g_kv   [TOKENS * KV_DIM];
__device__ __nv_bfloat16 g_att_h[TOKENS * C_DIM];
__device__ __nv_bfloat16 g_att_l[TOKENS * C_DIM];
__device__ float         g_x2   [TOKENS * C_DIM];
__device__ __nv_bfloat16 g_h_h  [TOKENS * C_DIM];
__device__ __nv_bfloat16 g_h_l  [TOKENS * C_DIM];
__device__ __nv_bfloat16 g_hh_h [TOKENS * HID];
__device__ __nv_bfloat16 g_hh_l [TOKENS * HID];

// Transposed + bf16-split weights: [N, K] row-major (i.e. W^T)
__device__ __nv_bfloat16 g_wkv_h [KV_DIM * C_DIM];
__device__ __nv_bfloat16 g_wkv_l [KV_DIM * C_DIM];
__device__ __nv_bfloat16 g_wout_h[C_DIM * C_DIM];
__device__ __nv_bfloat16 g_wout_l[C_DIM * C_DIM];
__device__ __nv_bfloat16 g_w1_h  [HID * C_DIM];
__device__ __nv_bfloat16 g_w1_l  [HID * C_DIM];
__device__ __nv_bfloat16 g_w2_h  [C_DIM * HID];
__device__ __nv_bfloat16 g_w2_l  [C_DIM * HID];

// ---------------------------------------------------------------------------
// Helpers
// ---------------------------------------------------------------------------
__device__ __forceinline__ void bsplit(float v, __nv_bfloat16& h, __nv_bfloat16& l) {
    h = __float2bfloat16(v);
    l = __float2bfloat16(v - __bfloat162float(h));
}

// bf16 m16n8k16 MMA (row.col), fp32 accumulate — supported on plain sm_103
__device__ __forceinline__ void mma_bf16(float* c, const uint32_t* a,
                                         uint32_t b0, uint32_t b1) {
    asm volatile(
        "mma.sync.aligned.m16n8k16.row.col.f32.bf16.bf16.f32 "
        "{%0,%1,%2,%3}, {%4,%5,%6,%7}, {%8,%9}, {%0,%1,%2,%3};"
        : "+f"(c[0]), "+f"(c[1]), "+f"(c[2]), "+f"(c[3])
        : "r"(a[0]), "r"(a[1]), "r"(a[2]), "r"(a[3]), "r"(b0), "r"(b1));
}

#define CP_ASYNC16(smem_u32, gptr) \
    asm volatile("cp.async.cg.shared.global [%0], [%1], 16;" \
        :: "r"(smem_u32), "l"(gptr) : "memory")
#define CP_COMMIT() asm volatile("cp.async.commit_group;" ::: "memory")
#define CP_WAIT1()  asm volatile("cp.async.wait_group 1;" ::: "memory")
#define CP_WAIT0()  asm volatile("cp.async.wait_group 0;" ::: "memory")

// ---------------------------------------------------------------------------
// Weight transpose + bf16 split: w[K,N] fp32 -> th/tl[N,K] bf16
// ---------------------------------------------------------------------------
__global__ void __launch_bounds__(256) wsplit_t(
    const float* __restrict__ w, __nv_bfloat16* __restrict__ th,
    __nv_bfloat16* __restrict__ tl, int K, int N)
{
    __shared__ float tile[32][33];
    const int n0 = blockIdx.x * 32, k0 = blockIdx.y * 32;
    const int tx = threadIdx.x, ty = threadIdx.y;
    #pragma unroll
    for (int i = ty; i < 32; i += 8)
        tile[i][tx] = w[(size_t)(k0 + i) * N + n0 + tx];
    __syncthreads();
    #pragma unroll
    for (int i = ty; i < 32; i += 8) {
        float v = tile[tx][i];                 // = w[k0+tx][n0+i]
        __nv_bfloat16 h, l; bsplit(v, h, l);
        size_t o = (size_t)(n0 + i) * K + k0 + tx;
        th[o] = h; tl[o] = l;
    }
}

// ---------------------------------------------------------------------------
// LayerNorm -> bf16 hi/lo outputs
// ---------------------------------------------------------------------------
__global__ void __launch_bounds__(256) ln_kernel(
    const float* __restrict__ x, const float* __restrict__ g,
    const float* __restrict__ b,
    __nv_bfloat16* __restrict__ hi, __nv_bfloat16* __restrict__ lo)
{
    __shared__ float sh[9];
    const int row = blockIdx.x;
    const int t = threadIdx.x;
    const float* xr = x + (size_t)row * C_DIM;

    float v0 = xr[t], v1 = xr[t + 256], v2 = xr[t + 512];

    float s = v0 + v1 + v2;
    #pragma unroll
    for (int o = 16; o; o >>= 1) s += __shfl_xor_sync(0xffffffffu, s, o);
    if ((t & 31) == 0) sh[t >> 5] = s;
    __syncthreads();
    if (t == 0) {
        float a = 0.f;
        #pragma unroll
        for (int i = 0; i < 8; i++) a += sh[i];
        sh[8] = a * (1.0f / C_DIM);
    }
    __syncthreads();
    const float mu = sh[8];

    float d0 = v0 - mu, d1 = v1 - mu, d2 = v2 - mu;
    float q = d0 * d0 + d1 * d1 + d2 * d2;
    __syncthreads();
    #pragma unroll
    for (int o = 16; o; o >>= 1) q += __shfl_xor_sync(0xffffffffu, q, o);
    if ((t & 31) == 0) sh[t >> 5] = q;
    __syncthreads();
    if (t == 0) {
        float a = 0.f;
        #pragma unroll
        for (int i = 0; i < 8; i++) a += sh[i];
        sh[8] = rsqrtf(a * (1.0f / C_DIM) + 1e-5f);
    }
    __syncthreads();
    const float rs = sh[8];

    const size_t rb = (size_t)row * C_DIM;
    float vals[3] = { d0 * rs * g[t] + b[t],
                      d1 * rs * g[t + 256] + b[t + 256],
                      d2 * rs * g[t + 512] + b[t + 512] };
    #pragma unroll
    for (int i = 0; i < 3; i++) {
        __nv_bfloat16 h, l; bsplit(vals[i], h, l);
        hi[rb + t + i * 256] = h;
        lo[rb + t + i * 256] = l;
    }
}

// ---------------------------------------------------------------------------
// bf16x3 tensor-core GEMM: C[M,N] = A @ Bt^T (+bias)(+resid | GELU)
// A: bf16 hi/lo [M,K] row-major; Bt: bf16 hi/lo [N,K] row-major.
// mma.m16n8k16 bf16, fp32 accum. Block tile 128x128, BK=32, 256 thr, 8 warps
// (2x4, warp tile 64x32). cp.async double-buffered smem, stride-40 layout
// (bank = (20g+ti)%32 — conflict-free fragment reads).
// ---------------------------------------------------------------------------
enum { EPI_NONE = 0, EPI_BIAS_RES = 1, EPI_BIAS_GELU = 2 };
enum { OUT_F32 = 0, OUT_BF16 = 1 };

#define BK 32
#define ST 40                       // smem row stride in bf16 elems
#define ARR_ELEMS (128 * ST)        // 5120 bf16 = 10240 B per array
#define STAGE_ELEMS (4 * ARR_ELEMS) // Ah, Al, Bh, Bl
#define TG_SMEM (2 * STAGE_ELEMS * 2)  // bytes = 81920

template <int EPI, int OUTM>
__global__ void __launch_bounds__(256) tgemm_bf3(
    int M, int N, int K,
    const __nv_bfloat16* __restrict__ Ahi, const __nv_bfloat16* __restrict__ Alo,
    const __nv_bfloat16* __restrict__ Bth, const __nv_bfloat16* __restrict__ Btl,
    const float* __restrict__ bias, const float* __restrict__ resid,
    float* __restrict__ C,
    __nv_bfloat16* __restrict__ Chi, __nv_bfloat16* __restrict__ Clo)
{
    extern __shared__ __nv_bfloat16 smem[];
    const uint32_t smb = (uint32_t)__cvta_generic_to_shared(smem);

    const int t    = threadIdx.x;
    const int lane = t & 31;
    const int warp = t >> 5;
    const int wm   = (warp >> 2) * 64;   // 0 or 64
    const int wn   = (warp & 3) * 32;    // 0,32,64,96
    const int g    = lane >> 2;          // 0..7
    const int ti   = lane & 3;           // 0..3

    const __nv_bfloat16* Ab_h = Ahi + (size_t)blockIdx.y * 128 * K;
    const __nv_bfloat16* Ab_l = Alo + (size_t)blockIdx.y * 128 * K;
    const __nv_bfloat16* Bb_h = Bth + (size_t)blockIdx.x * 128 * K;
    const __nv_bfloat16* Bb_l = Btl + (size_t)blockIdx.x * 128 * K;
    const __nv_bfloat16* srcs[4] = { Ab_h, Ab_l, Bb_h, Bb_l };

    // loader: per array 128 rows x 32 cols bf16 = 512 uint4; 2 per thread
    const int r0l = (t) >> 2,        q0l = (t) & 3;
    const int r1l = (t + 256) >> 2,  q1l = (t + 256) & 3;

    auto issue = [&](int c) {
        const int s = c & 1;
        const uint32_t sb = smb + s * (STAGE_ELEMS * 2);
        #pragma unroll
        for (int arr = 0; arr < 4; ++arr) {
            const __nv_bfloat16* src = srcs[arr] + c * BK;
            const uint32_t db = sb + arr * (ARR_ELEMS * 2);
            CP_ASYNC16(db + (uint32_t)(r0l * (ST * 2) + q0l * 16),
                       src + (size_t)r0l * K + q0l * 8);
            CP_ASYNC16(db + (uint32_t)(r1l * (ST * 2) + q1l * 16),
                       src + (size_t)r1l * K + q1l * 8);
        }
        CP_COMMIT();
    };

    float acc[4][4][4];
    #pragma unroll
    for (int i = 0; i < 4; i++)
        #pragma unroll
        for (int j = 0; j < 4; j++)
            #pragma unroll
            for (int k = 0; k < 4; k++) acc[i][j][k] = 0.f;

    const int nStages = K / BK;
    issue(0);
    if (nStages > 1) issue(1);

    for (int c = 0; c < nStages; ++c) {
        if (c + 1 < nStages) { CP_WAIT1(); } else { CP_WAIT0(); }
        __syncthreads();

        const int s = c & 1;
        const __nv_bfloat16* sAh = smem + s * STAGE_ELEMS;
        const __nv_bfloat16* sAl = sAh + ARR_ELEMS;
        const __nv_bfloat16* sBh = sAl + ARR_ELEMS;
        const __nv_bfloat16* sBl = sBh + ARR_ELEMS;

        #pragma unroll
        for (int ks = 0; ks < BK; ks += 16) {
            uint32_t ah[4][4], al[4][4];
            #pragma unroll
            for (int ib = 0; ib < 4; ++ib) {
                const int rb = (wm + ib * 16 + g) * ST + ks + 2 * ti;
                ah[ib][0] = *reinterpret_cast<const uint32_t*>(sAh + rb);
                ah[ib][1] = *reinterpret_cast<const uint32_t*>(sAh + rb + 8 * ST);
                ah[ib][2] = *reinterpret_cast<const uint32_t*>(sAh + rb + 8);
                ah[ib][3] = *reinterpret_cast<const uint32_t*>(sAh + rb + 8 * ST + 8);
                al[ib][0] = *reinterpret_cast<const uint32_t*>(sAl + rb);
                al[ib][1] = *reinterpret_cast<const uint32_t*>(sAl + rb + 8 * ST);
                al[ib][2] = *reinterpret_cast<const uint32_t*>(sAl + rb + 8);
                al[ib][3] = *reinterpret_cast<const uint32_t*>(sAl + rb + 8 * ST + 8);
            }
            #pragma unroll
            for (int jb = 0; jb < 4; ++jb) {
                const int nb = (wn + jb * 8 + g) * ST + ks + 2 * ti;
                const uint32_t bh0 = *reinterpret_cast<const uint32_t*>(sBh + nb);
                const uint32_t bh1 = *reinterpret_cast<const uint32_t*>(sBh + nb + 8);
                const uint32_t bl0 = *reinterpret_cast<const uint32_t*>(sBl + nb);
                const uint32_t bl1 = *reinterpret_cast<const uint32_t*>(sBl + nb + 8);
                #pragma unroll
                for (int ib = 0; ib < 4; ++ib) {
                    mma_bf16(acc[ib][jb], ah[ib], bh0, bh1);   // hi*hi
                    mma_bf16(acc[ib][jb], ah[ib], bl0, bl1);   // hi*lo
                    mma_bf16(acc[ib][jb], al[ib], bh0, bh1);   // lo*hi
                }
            }
        }
        __syncthreads();
        if (c + 2 < nStages) issue(c + 2);
    }

    // Epilogue: c0,c1 at (g, 2ti/(+1)); c2,c3 at (g+8, ...)
    const int row0 = blockIdx.y * 128 + wm;
    const int col0 = blockIdx.x * 128 + wn;
    #pragma unroll
    for (int ib = 0; ib < 4; ++ib) {
        #pragma unroll
        for (int jb = 0; jb < 4; ++jb) {
            const int cc = col0 + jb * 8 + 2 * ti;
            #pragma unroll
            for (int half = 0; half < 2; half++) {
                const int r = row0 + ib * 16 + g + half * 8;
                float e0 = acc[ib][jb][half * 2 + 0];
                float e1 = acc[ib][jb][half * 2 + 1];
                const size_t off = (size_t)r * N + cc;
                if (EPI != EPI_NONE) {
                    e0 += bias[cc];
                    e1 += bias[cc + 1];
                }
                if (EPI == EPI_BIAS_RES) {
                    float2 rr = *reinterpret_cast<const float2*>(resid + off);
                    e0 += rr.x;
                    e1 += rr.y;
                }
                if (EPI == EPI_BIAS_GELU) {
                    e0 = 0.5f * e0 * (1.0f + erff(e0 * 0.70710678118654752f));
                    e1 = 0.5f * e1 * (1.0f + erff(e1 * 0.70710678118654752f));
                }
                if (OUTM == OUT_F32) {
                    *reinterpret_cast<float2*>(C + off) = make_float2(e0, e1);
                } else {
                    __nv_bfloat162 hh2, ll2;
                    bsplit(e0, hh2.x, ll2.x);
                    bsplit(e1, hh2.y, ll2.y);
                    *reinterpret_cast<__nv_bfloat162*>(Chi + off) = hh2;
                    *reinterpret_cast<__nv_bfloat162*>(Clo + off) = ll2;
                }
            }
        }
    }
}

// ---------------------------------------------------------------------------
// Flash attention, fp32; epilogue emits bf16 hi/lo for the out-proj GEMM.
// ---------------------------------------------------------------------------
struct AttSmem {
    float Qs [64][65];
    float KVs[64][65];
    float Ps [64][65];
    float red[64][16];
    float m_run[64];
    float l_run[64];
    float alpha[64];
    float m_cur[64];
};

__global__ void __launch_bounds__(256) attn_kernel(
    const float* __restrict__ qx, const float* __restrict__ kv,
    __nv_bfloat16* __restrict__ out_h, __nv_bfloat16* __restrict__ out_l)
{
    extern __shared__ unsigned char smem_raw[];
    AttSmem& sm = *reinterpret_cast<AttSmem*>(smem_raw);

    const int t  = threadIdx.x;
    const int tx = t & 15, ty = t >> 4;
    const int r0 = ty * 4, c0 = tx * 4;
    const int qb = blockIdx.x * 64;
    const int h  = blockIdx.y;
    const int b  = blockIdx.z;

    const float* qptr = qx + ((size_t)b * SEQ) * C_DIM  + (size_t)h * DH;
    const float* kptr = kv + ((size_t)b * SEQ) * KV_DIM + (size_t)h * DH;
    const float* vptr = kptr + C_DIM;

    #pragma unroll
    for (int i = 0; i < 4; i++) {
        int vi = t + i * 256;
        int r  = vi >> 4;
        int d  = (vi & 15) * 4;
        float4 q4 = *reinterpret_cast<const float4*>(qptr + (size_t)(qb + r) * C_DIM + d);
        sm.Qs[r][d + 0] = q4.x; sm.Qs[r][d + 1] = q4.y;
        sm.Qs[r][d + 2] = q4.z; sm.Qs[r][d + 3] = q4.w;
    }
    if (t < 64) { sm.m_run[t] = -INFINITY; sm.l_run[t] = 0.f; }

    float o[4][4] = {};
    __syncthreads();

    for (int kt = 0; kt < 16; ++kt) {
        const int kb = kt * 64;

        #pragma unroll
        for (int i = 0; i < 4; i++) {
            int vi = t + i * 256;
            int r  = vi >> 4;
            int d  = (vi & 15) * 4;
            float4 k4 = *reinterpret_cast<const float4*>(kptr + (size_t)(kb + r) * KV_DIM + d);
            sm.KVs[r][d + 0] = k4.x; sm.KVs[r][d + 1] = k4.y;
            sm.KVs[r][d + 2] = k4.z; sm.KVs[r][d + 3] = k4.w;
        }
        __syncthreads();

        float s[4][4] = {};
        #pragma unroll 4
        for (int d = 0; d < 64; ++d) {
            float qf[4], kf[4];
            #pragma unroll
            for (int i = 0; i < 4; i++) qf[i] = sm.Qs[r0 + i][d];
            #pragma unroll
            for (int j = 0; j < 4; j++) kf[j] = sm.KVs[c0 + j][d];
            #pragma unroll
            for (int i = 0; i < 4; i++)
                #pragma unroll
                for (int j = 0; j < 4; j++) s[i][j] += qf[i] * kf[j];
        }
        #pragma unroll
        for (int i = 0; i < 4; i++)
            #pragma unroll
            for (int j = 0; j < 4; j++) s[i][j] *= 0.125f;

        __syncthreads();

        #pragma unroll
        for (int i = 0; i < 4; i++) {
            float mx = fmaxf(fmaxf(s[i][0], s[i][1]), fmaxf(s[i][2], s[i][3]));
            sm.red[r0 + i][tx] = mx;
        }
        __syncthreads();

        if (t < 64) {
            float mx = sm.red[t][0];
            #pragma unroll
            for (int jj = 1; jj < 16; jj++) mx = fmaxf(mx, sm.red[t][jj]);
            float mo = sm.m_run[t];
            float mn = fmaxf(mo, mx);
            sm.m_cur[t]  = mn;
            sm.alpha[t]  = expf(mo - mn);
            sm.m_run[t]  = mn;
        }
        __syncthreads();

        #pragma unroll
        for (int i = 0; i < 4; i++) {
            float mn = sm.m_cur[r0 + i];
            float ps = 0.f;
            #pragma unroll
            for (int j = 0; j < 4; j++) {
                float p = expf(s[i][j] - mn);
                sm.Ps[r0 + i][c0 + j] = p;
                ps += p;
            }
            sm.red[r0 + i][tx] = ps;
        }
        #pragma unroll
        for (int i = 0; i < 4; i++) {
            int vi = t + i * 256;
            int r  = vi >> 4;
            int d  = (vi & 15) * 4;
            float4 v4 = *reinterpret_cast<const float4*>(vptr + (size_t)(kb + r) * KV_DIM + d);
            sm.KVs[r][d + 0] = v4.x; sm.KVs[r][d + 1] = v4.y;
            sm.KVs[r][d + 2] = v4.z; sm.KVs[r][d + 3] = v4.w;
        }
        __syncthreads();

        if (t < 64) {
            float su = 0.f;
            #pragma unroll
            for (int jj = 0; jj < 16; jj++) su += sm.red[t][jj];
            sm.l_run[t] = sm.alpha[t] * sm.l_run[t] + su;
        }

        #pragma unroll
        for (int i = 0; i < 4; i++) {
            float a = sm.alpha[r0 + i];
            #pragma unroll
            for (int j = 0; j < 4; j++) o[i][j] *= a;
        }
        #pragma unroll 4
        for (int kk = 0; kk < 64; ++kk) {
            float pf[4], vf[4];
            #pragma unroll
            for (int i = 0; i < 4; i++) pf[i] = sm.Ps[r0 + i][kk];
            #pragma unroll
            for (int j = 0; j < 4; j++) vf[j] = sm.KVs[kk][c0 + j];
            #pragma unroll
            for (int i = 0; i < 4; i++)
                #pragma unroll
                for (int j = 0; j < 4; j++) o[i][j] += pf[i] * vf[j];
        }
        __syncthreads();
    }

    #pragma unroll
    for (int i = 0; i < 4; i++) {
        float inv = 1.0f / sm.l_run[r0 + i];
        const size_t off = ((size_t)b * SEQ + qb + r0 + i) * C_DIM + h * DH + c0;
        __nv_bfloat162 h01, h23, l01, l23;
        bsplit(o[i][0] * inv, h01.x, l01.x);
        bsplit(o[i][1] * inv, h01.y, l01.y);
        bsplit(o[i][2] * inv, h23.x, l23.x);
        bsplit(o[i][3] * inv, h23.y, l23.y);
        *reinterpret_cast<__nv_bfloat162*>(out_h + off)     = h01;
        *reinterpret_cast<__nv_bfloat162*>(out_h + off + 2) = h23;
        *reinterpret_cast<__nv_bfloat162*>(out_l + off)     = l01;
        *reinterpret_cast<__nv_bfloat162*>(out_l + off + 2) = l23;
    }
}

// ---------------------------------------------------------------------------
// Launch
// ---------------------------------------------------------------------------
extern "C" void kernel_launch(void* const* d_in, const int* in_sizes, int n_in,
                              void* d_out, int out_size)
{
    const float* x       = (const float*)d_in[0];
    const float* q_extra = (const float*)d_in[1];
    const float* ln1_g   = (const float*)d_in[2];
    const float* ln1_b   = (const float*)d_in[3];
    const float* w_kv    = (const float*)d_in[4];
    const float* w_out   = (const float*)d_in[5];
    const float* b_out   = (const float*)d_in[6];
    const float* ln2_g   = (const float*)d_in[7];
    const float* ln2_b   = (const float*)d_in[8];
    const float* w1      = (const float*)d_in[9];
    const float* b1      = (const float*)d_in[10];
    const float* w2      = (const float*)d_in[11];
    const float* b2      = (const float*)d_in[12];
    float* out = (float*)d_out;

    __nv_bfloat16 *xn_h, *xn_l, *att_h, *att_l, *h_h, *h_l, *hh_h, *hh_l;
    __nv_bfloat16 *wkv_h, *wkv_l, *wout_h, *wout_l, *w1_h, *w1_l, *w2_h, *w2_l;
    float *kvp, *x2;
    cudaGetSymbolAddress((void**)&xn_h,  g_xn_h);  cudaGetSymbolAddress((void**)&xn_l,  g_xn_l);
    cudaGetSymbolAddress((void**)&att_h, g_att_h); cudaGetSymbolAddress((void**)&att_l, g_att_l);
    cudaGetSymbolAddress((void**)&h_h,   g_h_h);   cudaGetSymbolAddress((void**)&h_l,   g_h_l);
    cudaGetSymbolAddress((void**)&hh_h,  g_hh_h);  cudaGetSymbolAddress((void**)&hh_l,  g_hh_l);
    cudaGetSymbolAddress((void**)&wkv_h, g_wkv_h); cudaGetSymbolAddress((void**)&wkv_l, g_wkv_l);
    cudaGetSymbolAddress((void**)&wout_h,g_wout_h);cudaGetSymbolAddress((void**)&wout_l,g_wout_l);
    cudaGetSymbolAddress((void**)&w1_h,  g_w1_h);  cudaGetSymbolAddress((void**)&w1_l,  g_w1_l);
    cudaGetSymbolAddress((void**)&w2_h,  g_w2_h);  cudaGetSymbolAddress((void**)&w2_l,  g_w2_l);
    cudaGetSymbolAddress((void**)&kvp,   g_kv);
    cudaGetSymbolAddress((void**)&x2,    g_x2);

    cudaFuncSetAttribute(attn_kernel, cudaFuncAttributeMaxDynamicSharedMemorySize,
                         (int)sizeof(AttSmem));
    cudaFuncSetAttribute(tgemm_bf3<EPI_NONE, OUT_F32>,
                         cudaFuncAttributeMaxDynamicSharedMemorySize, TG_SMEM);
    cudaFuncSetAttribute(tgemm_bf3<EPI_BIAS_RES, OUT_F32>,
                         cudaFuncAttributeMaxDynamicSharedMemorySize, TG_SMEM);
    cudaFuncSetAttribute(tgemm_bf3<EPI_BIAS_GELU, OUT_BF16>,
                         cudaFuncAttributeMaxDynamicSharedMemorySize, TG_SMEM);

    // 0) Weight transpose + bf16 split: [K,N] -> [N,K] hi/lo
    wsplit_t<<<dim3(KV_DIM / 32, C_DIM / 32), dim3(32, 8)>>>(w_kv,  wkv_h,  wkv_l,  C_DIM, KV_DIM);
    wsplit_t<<<dim3(C_DIM / 32,  C_DIM / 32), dim3(32, 8)>>>(w_out, wout_h, wout_l, C_DIM, C_DIM);
    wsplit_t<<<dim3(HID / 32,    C_DIM / 32), dim3(32, 8)>>>(w1,    w1_h,   w1_l,   C_DIM, HID);
    wsplit_t<<<dim3(C_DIM / 32,  HID / 32),   dim3(32, 8)>>>(w2,    w2_h,   w2_l,   HID,   C_DIM);

    // 1) xn = LN1(x)  (bf16 hi/lo)
    ln_kernel<<<TOKENS, 256>>>(x, ln1_g, ln1_b, xn_h, xn_l);

    // 2) kv = xn @ w_kv            [8192 x 1536, K=768]
    tgemm_bf3<EPI_NONE, OUT_F32><<<dim3(KV_DIM / 128, TOKENS / 128), 256, TG_SMEM>>>(
        TOKENS, KV_DIM, C_DIM, xn_h, xn_l, wkv_h, wkv_l,
        nullptr, nullptr, kvp, nullptr, nullptr);

    // 3) att = softmax(q k^T / 8) v   (bf16 hi/lo)
    attn_kernel<<<dim3(SEQ / 64, HEADS, BATCH), 256, sizeof(AttSmem)>>>(
        q_extra, kvp, att_h, att_l);

    // 4) x2 = x + att @ w_out + b_out   [8192 x 768, K=768]
    tgemm_bf3<EPI_BIAS_RES, OUT_F32><<<dim3(C_DIM / 128, TOKENS / 128), 256, TG_SMEM>>>(
        TOKENS, C_DIM, C_DIM, att_h, att_l, wout_h, wout_l,
        b_out, x, x2, nullptr, nullptr);

    // 5) h = LN2(x2)   (bf16 hi/lo)
    ln_kernel<<<TOKENS, 256>>>(x2, ln2_g, ln2_b, h_h, h_l);

    // 6) hh = gelu(h @ w1 + b1)   [8192 x 3072, K=768] (bf16 hi/lo)
    tgemm_bf3<EPI_BIAS_GELU, OUT_BF16><<<dim3(HID / 128, TOKENS / 128), 256, TG_SMEM>>>(
        TOKENS, HID, C_DIM, h_h, h_l, w1_h, w1_l,
        b1, nullptr, nullptr, hh_h, hh_l);

    // 7) out = x2 + hh @ w2 + b2   [8192 x 768, K=3072]
    tgemm_bf3<EPI_BIAS_RES, OUT_F32><<<dim3(C_DIM / 128, TOKENS / 128), 256, TG_SMEM>>>(
        TOKENS, C_DIM, HID, hh_h, hh_l, w2_h, w2_l,
        b2, x2, out, nullptr, nullptr);
}